// round 3
// baseline (speedup 1.0000x reference)
#include <cuda_runtime.h>
#include <math.h>

namespace cfg {
constexpr int B = 16, T = 500, C = 512, K = 7, NH = 8, HD = 64, HID = 2048, L = 3, NC = 2;
constexpr int BT = B * T;                  // 8000
constexpr long BTC = (long)BT * C;         // 4,096,000
constexpr float SCALE = 0.125f;            // 1/sqrt(HD=64)
}

// ---------------------------------------------------------------------------
// Scratch (static device globals — no allocation allowed in kernel_launch)
// ---------------------------------------------------------------------------
__device__ float g_t0[cfg::BT * cfg::C];
__device__ float g_t1[cfg::BT * cfg::C];
__device__ float g_q [cfg::BT * cfg::C];
__device__ float g_k [cfg::BT * cfg::C];
__device__ float g_v [cfg::BT * cfg::C];
__device__ float g_hid[cfg::BT * cfg::HID];

// ---------------------------------------------------------------------------
// Depthwise causal-padded conv along T (groups=C), K=7, pad=3. Adds dw bias.
// Grid: BT blocks, 512 threads (one per channel). Coalesced along C.
// ---------------------------------------------------------------------------
__global__ void dwconv_kernel(const float* __restrict__ x, const float* __restrict__ w,
                              const float* __restrict__ bias, float* __restrict__ y) {
    int bt = blockIdx.x;
    int t  = bt % cfg::T;
    int c  = threadIdx.x;
    const float* xr = x + (long)(bt - t) * cfg::C + c;   // start of this batch row
    float wr[7];
#pragma unroll
    for (int k = 0; k < 7; k++) wr[k] = w[c * 7 + k];
    float acc = bias[c];
#pragma unroll
    for (int k = 0; k < 7; k++) {
        int tt = t + k - 3;
        if (tt >= 0 && tt < cfg::T) acc += xr[(long)tt * cfg::C] * wr[k];
    }
    y[(long)bt * cfg::C + c] = acc;
}

// ---------------------------------------------------------------------------
// Tiled SGEMM: Cm[M,N] = A[M,K] @ W[N,K]^T + bias[N], optional ReLU.
// 64x64 block tile, BK=16, 256 threads, 4x4 micro-tile.
// Requires M%64==0, N%64==0, K%16==0 (true for all shapes here).
// Smem staged transposed (As[k][m], Ws[k][n]) for conflict-free inner reads.
// ---------------------------------------------------------------------------
template <int RELU>
__global__ void gemm_kernel(const float* __restrict__ A, const float* __restrict__ W,
                            const float* __restrict__ bias, float* __restrict__ Cm,
                            int M, int N, int Kd) {
    __shared__ float As[16][64];
    __shared__ float Ws[16][64];
    int tid = threadIdx.x;
    int tx = tid & 15, ty = tid >> 4;
    int row0 = blockIdx.y * 64, col0 = blockIdx.x * 64;
    int lr = tid >> 2;            // 0..63 (tile row)
    int lc = (tid & 3) << 2;      // 0,4,8,12 (k offset)
    const float* ap = A + (long)(row0 + lr) * Kd + lc;
    const float* wp = W + (long)(col0 + lr) * Kd + lc;
    float acc[4][4] = {};
    for (int k0 = 0; k0 < Kd; k0 += 16) {
        float4 av = *(const float4*)(ap + k0);
        float4 wv = *(const float4*)(wp + k0);
        As[lc + 0][lr] = av.x; As[lc + 1][lr] = av.y; As[lc + 2][lr] = av.z; As[lc + 3][lr] = av.w;
        Ws[lc + 0][lr] = wv.x; Ws[lc + 1][lr] = wv.y; Ws[lc + 2][lr] = wv.z; Ws[lc + 3][lr] = wv.w;
        __syncthreads();
#pragma unroll
        for (int kk = 0; kk < 16; kk++) {
            float a[4], w[4];
#pragma unroll
            for (int i = 0; i < 4; i++) a[i] = As[kk][ty * 4 + i];
#pragma unroll
            for (int j = 0; j < 4; j++) w[j] = Ws[kk][tx * 4 + j];
#pragma unroll
            for (int i = 0; i < 4; i++)
#pragma unroll
                for (int j = 0; j < 4; j++) acc[i][j] += a[i] * w[j];
        }
        __syncthreads();
    }
#pragma unroll
    for (int i = 0; i < 4; i++) {
        int r = row0 + ty * 4 + i;
#pragma unroll
        for (int j = 0; j < 4; j++) {
            int cc = col0 + tx * 4 + j;
            float v = acc[i][j] + bias[cc];
            if (RELU) v = fmaxf(v, 0.f);
            Cm[(long)r * N + cc] = v;
        }
    }
}

// ---------------------------------------------------------------------------
// In-place LayerNorm over C=512 per row. Grid: BT blocks, 256 threads.
// ---------------------------------------------------------------------------
__global__ void ln_kernel(float* __restrict__ x, const float* __restrict__ g,
                          const float* __restrict__ b) {
    long row = blockIdx.x;
    float* xr = x + row * cfg::C;
    int tid = threadIdx.x;
    float v0 = xr[tid], v1 = xr[tid + 256];
    float s = v0 + v1, ss = v0 * v0 + v1 * v1;
#pragma unroll
    for (int o = 16; o > 0; o >>= 1) {
        s  += __shfl_xor_sync(~0u, s, o);
        ss += __shfl_xor_sync(~0u, ss, o);
    }
    __shared__ float sh_s[8], sh_ss[8];
    int w = tid >> 5, ln = tid & 31;
    if (ln == 0) { sh_s[w] = s; sh_ss[w] = ss; }
    __syncthreads();
    float ts = 0.f, tss = 0.f;
#pragma unroll
    for (int i = 0; i < 8; i++) { ts += sh_s[i]; tss += sh_ss[i]; }
    float mean = ts * (1.f / 512.f);
    float var  = tss * (1.f / 512.f) - mean * mean;
    float rinv = rsqrtf(var + 1e-5f);
    xr[tid]       = (v0 - mean) * rinv * g[tid]       + b[tid];
    xr[tid + 256] = (v1 - mean) * rinv * g[tid + 256] + b[tid + 256];
}

// ---------------------------------------------------------------------------
// Causal flash attention, fp32. Q/K/V in (B,T,C) with head slice h*HD.
// Block = (qtile=64 rows, head, batch). 256 threads: r=tid/4 (row), cg=tid%4.
// BK=32 key tile. Static smem < 48KB.
// ---------------------------------------------------------------------------
__global__ void attn_kernel(const float* __restrict__ Q, const float* __restrict__ Kb,
                            const float* __restrict__ V, float* __restrict__ Y) {
    __shared__ float Qs[64][65];
    __shared__ float Ks[32][65];
    __shared__ float Vs[32][65];
    __shared__ float Ps[64][33];
    int qt = blockIdx.x, h = blockIdx.y, bb = blockIdx.z;
    int tid = threadIdx.x;
    int r = tid >> 2, cg = tid & 3;
    const long base = (long)bb * cfg::T * cfg::C + h * cfg::HD;

    // load Q tile (zero-fill rows past T)
#pragma unroll
    for (int i = 0; i < 16; i++) {
        int e = tid + i * 256;
        int rr = e >> 6, d = e & 63;
        int iq = qt * 64 + rr;
        Qs[rr][d] = (iq < cfg::T) ? Q[base + (long)iq * cfg::C + d] : 0.f;
    }
    float m = -3e38f, l = 0.f;
    float acc[16];
#pragma unroll
    for (int j = 0; j < 16; j++) acc[j] = 0.f;
    int iq = qt * 64 + r;
    int ktmax = 2 * qt + 1;   // causal: need kt*32 <= qt*64+63
    __syncthreads();

    for (int kt = 0; kt <= ktmax; kt++) {
        // load K,V tiles (32x64)
#pragma unroll
        for (int i = 0; i < 8; i++) {
            int e = tid + i * 256;
            int rr = e >> 6, d = e & 63;
            int jg = kt * 32 + rr;
            float kv = 0.f, vv = 0.f;
            if (jg < cfg::T) {
                kv = Kb[base + (long)jg * cfg::C + d];
                vv = V [base + (long)jg * cfg::C + d];
            }
            Ks[rr][d] = kv; Vs[rr][d] = vv;
        }
        __syncthreads();

        // scores: 8 columns per thread (c = cg*8+j)
        float s[8];
#pragma unroll
        for (int j = 0; j < 8; j++) s[j] = 0.f;
#pragma unroll
        for (int d = 0; d < 64; d++) {
            float qd = Qs[r][d];
#pragma unroll
            for (int j = 0; j < 8; j++) s[j] += qd * Ks[cg * 8 + j][d];
        }
        float mloc = -3e38f;
#pragma unroll
        for (int j = 0; j < 8; j++) {
            int jg = kt * 32 + cg * 8 + j;
            s[j] = (jg <= iq && jg < cfg::T) ? s[j] * cfg::SCALE : -1e30f;
            mloc = fmaxf(mloc, s[j]);
        }
        mloc = fmaxf(mloc, __shfl_xor_sync(~0u, mloc, 1));
        mloc = fmaxf(mloc, __shfl_xor_sync(~0u, mloc, 2));
        float mnew = fmaxf(m, mloc);
        float psum = 0.f;
#pragma unroll
        for (int j = 0; j < 8; j++) {
            float p = __expf(s[j] - mnew);
            Ps[r][cg * 8 + j] = p;
            psum += p;
        }
        psum += __shfl_xor_sync(~0u, psum, 1);
        psum += __shfl_xor_sync(~0u, psum, 2);
        float sc = __expf(m - mnew);
        l = l * sc + psum;
        m = mnew;
#pragma unroll
        for (int j = 0; j < 16; j++) acc[j] *= sc;
        __syncthreads();

        // AV: each thread owns (row r, d-cols cg*16 .. cg*16+15)
#pragma unroll
        for (int c = 0; c < 32; c++) {
            float p = Ps[r][c];
#pragma unroll
            for (int j = 0; j < 16; j++) acc[j] += p * Vs[c][cg * 16 + j];
        }
        __syncthreads();
    }
    if (iq < cfg::T) {
        float rl = 1.f / l;
#pragma unroll
        for (int j = 0; j < 16; j++)
            Y[base + (long)iq * cfg::C + cg * 16 + j] = acc[j] * rl;
    }
}

// ---------------------------------------------------------------------------
// Launch orchestration. Graph-capturable: kernel launches only.
// ---------------------------------------------------------------------------
extern "C" void kernel_launch(void* const* d_in, const int* in_sizes, int n_in,
                              void* d_out, int out_size) {
    using namespace cfg;
    const float* x     = (const float*)d_in[0];
    const float* dw_w  = (const float*)d_in[1];
    const float* dw_b  = (const float*)d_in[2];
    const float* pw_w  = (const float*)d_in[3];
    const float* pw_b  = (const float*)d_in[4];
    const float* cln_g = (const float*)d_in[5];
    const float* cln_b = (const float*)d_in[6];
    const float* wq = (const float*)d_in[7];  const float* bq = (const float*)d_in[8];
    const float* wk = (const float*)d_in[9];  const float* bk = (const float*)d_in[10];
    const float* wv = (const float*)d_in[11]; const float* bv = (const float*)d_in[12];
    const float* wo = (const float*)d_in[13]; const float* bo = (const float*)d_in[14];
    const float* aln_g = (const float*)d_in[15]; const float* aln_b = (const float*)d_in[16];
    const float* w1 = (const float*)d_in[17]; const float* b1 = (const float*)d_in[18];
    const float* w2 = (const float*)d_in[19]; const float* b2 = (const float*)d_in[20];
    const float* fln_g = (const float*)d_in[21]; const float* fln_b = (const float*)d_in[22];
    float* out = (float*)d_out;

    float *t0, *t1, *qb, *kb, *vb, *hid;
    cudaGetSymbolAddress((void**)&t0,  g_t0);
    cudaGetSymbolAddress((void**)&t1,  g_t1);
    cudaGetSymbolAddress((void**)&qb,  g_q);
    cudaGetSymbolAddress((void**)&kb,  g_k);
    cudaGetSymbolAddress((void**)&vb,  g_v);
    cudaGetSymbolAddress((void**)&hid, g_hid);

    dim3 blk(256);
    dim3 gridCC(C / 64, BT / 64);       // N=512 GEMMs
    dim3 gridCH(HID / 64, BT / 64);     // N=2048 GEMM

    const float* cur = x;
    for (int l = 0; l < L; l++) {
        // ---- 2 conv blocks: dwconv -> pointwise GEMM -> LN (in-place) ----
        for (int nc = 0; nc < NC; nc++) {
            const float* cin = (nc == 0) ? cur : t1;
            long idx = (long)(l * NC + nc);
            dwconv_kernel<<<BT, C>>>(cin, dw_w + idx * C * K, dw_b + idx * C, t0);
            gemm_kernel<0><<<gridCC, blk>>>(t0, pw_w + idx * C * C, pw_b + idx * C, t1, BT, C, C);
            ln_kernel<<<BT, 256>>>(t1, cln_g + idx * C, cln_b + idx * C);
        }
        // ---- attention ----
        gemm_kernel<0><<<gridCC, blk>>>(t1, wq + (long)l * C * C, bq + (long)l * C, qb, BT, C, C);
        gemm_kernel<0><<<gridCC, blk>>>(t1, wk + (long)l * C * C, bk + (long)l * C, kb, BT, C, C);
        gemm_kernel<0><<<gridCC, blk>>>(t1, wv + (long)l * C * C, bv + (long)l * C, vb, BT, C, C);
        attn_kernel<<<dim3(8, NH, B), 256>>>(qb, kb, vb, t0);
        gemm_kernel<0><<<gridCC, blk>>>(t0, wo + (long)l * C * C, bo + (long)l * C, t1, BT, C, C);
        ln_kernel<<<BT, 256>>>(t1, aln_g + (long)l * C, aln_b + (long)l * C);
        // ---- FFN ----
        gemm_kernel<1><<<gridCH, blk>>>(t1, w1 + (long)l * HID * C, b1 + (long)l * HID, hid, BT, HID, C);
        float* outl = out + (long)l * BTC;
        gemm_kernel<0><<<gridCC, blk>>>(hid, w2 + (long)l * C * HID, b2 + (long)l * C, outl, BT, C, HID);
        ln_kernel<<<BT, 256>>>(outl, fln_g + (long)l * C, fln_b + (long)l * C);
        cur = outl;
    }
}

// round 8
// speedup vs baseline: 1.9135x; 1.9135x over previous
#include <cuda_runtime.h>
#include <cuda_bf16.h>
#include <cstdint>
#include <math.h>

using std::uint32_t;
using std::uint64_t;

namespace cfg {
constexpr int B = 16, T = 500, C = 512, K = 7, NH = 8, HD = 64, HID = 2048, L = 3, NC = 2;
constexpr int BT = B * T;                  // 8000
constexpr int MPAD = 8064;                 // 63 * 128
constexpr long BTC = (long)BT * C;
constexpr float SCALE = 0.125f;
constexpr long OFF_PW = 0;
constexpr long LEN_PW = (long)L * NC * C * C;
constexpr long OFF_WQ = OFF_PW + LEN_PW;
constexpr long LEN_W  = (long)L * C * C;
constexpr long OFF_WK = OFF_WQ + LEN_W;
constexpr long OFF_WV = OFF_WK + LEN_W;
constexpr long OFF_WO = OFF_WV + LEN_W;
constexpr long OFF_W1 = OFF_WO + LEN_W;
constexpr long LEN_W1 = (long)L * HID * C;
constexpr long OFF_W2 = OFF_W1 + LEN_W1;
constexpr long LEN_W2 = (long)L * C * HID;
constexpr long WTOT   = OFF_W2 + LEN_W2;
}

// ---------------------------------------------------------------------------
// Scratch (device globals; no allocation allowed)
// ---------------------------------------------------------------------------
__device__ float g_t0[cfg::BT * cfg::C];
__device__ float g_t1[cfg::BT * cfg::C];
__device__ float g_q [cfg::BT * cfg::C];
__device__ float g_k [cfg::BT * cfg::C];
__device__ float g_v [cfg::BT * cfg::C];
__device__ float g_hid[cfg::BT * cfg::HID];
__device__ __nv_bfloat16 g_ahi[(long)cfg::MPAD * cfg::HID];
__device__ __nv_bfloat16 g_alo[(long)cfg::MPAD * cfg::HID];
__device__ __nv_bfloat16 g_whi[cfg::WTOT];
__device__ __nv_bfloat16 g_wlo[cfg::WTOT];

// ---------------------------------------------------------------------------
// PTX helpers (all plain sm_80+ instructions; NO tcgen05 — ptxas lowers via
// compute_103 which rejects the 'a'-suffix feature set)
// ---------------------------------------------------------------------------
__device__ __forceinline__ uint32_t smem_u32(const void* p) {
    uint32_t a;
    asm("{ .reg .u64 t; cvta.to.shared.u64 t, %1; cvt.u32.u64 %0, t; }" : "=r"(a) : "l"(p));
    return a;
}
__device__ __forceinline__ void cp_async16(uint32_t dst, const void* src) {
    asm volatile("cp.async.ca.shared.global [%0], [%1], 16;" :: "r"(dst), "l"(src));
}
__device__ __forceinline__ void cp_commit() {
    asm volatile("cp.async.commit_group;" ::: "memory");
}
__device__ __forceinline__ void ldm_x4(uint32_t* a, uint32_t addr) {
    asm volatile("ldmatrix.sync.aligned.m8n8.x4.shared.b16 {%0,%1,%2,%3}, [%4];"
                 : "=r"(a[0]), "=r"(a[1]), "=r"(a[2]), "=r"(a[3]) : "r"(addr));
}
__device__ __forceinline__ void ldm_x2(uint32_t* b, uint32_t addr) {
    asm volatile("ldmatrix.sync.aligned.m8n8.x2.shared.b16 {%0,%1}, [%2];"
                 : "=r"(b[0]), "=r"(b[1]) : "r"(addr));
}
__device__ __forceinline__ void mma_bf16(float* d, const uint32_t* a, const uint32_t* b) {
    asm volatile(
        "mma.sync.aligned.m16n8k16.row.col.f32.bf16.bf16.f32 "
        "{%0,%1,%2,%3},{%4,%5,%6,%7},{%8,%9},{%0,%1,%2,%3};"
        : "+f"(d[0]), "+f"(d[1]), "+f"(d[2]), "+f"(d[3])
        : "r"(a[0]), "r"(a[1]), "r"(a[2]), "r"(a[3]), "r"(b[0]), "r"(b[1]));
}

// ---------------------------------------------------------------------------
// fp32 -> (hi, lo) bf16 split converters
// ---------------------------------------------------------------------------
__global__ void cvt_w_kernel(const float* __restrict__ in, __nv_bfloat16* __restrict__ hi,
                             __nv_bfloat16* __restrict__ lo, long n) {
    long i = (long)blockIdx.x * blockDim.x + threadIdx.x;
    if (i >= n) return;
    float v = in[i];
    __nv_bfloat16 h = __float2bfloat16(v);
    hi[i] = h;
    lo[i] = __float2bfloat16(v - __bfloat162float(h));
}

__global__ void cvt_act_kernel(const float* __restrict__ in, __nv_bfloat16* __restrict__ hi,
                               __nv_bfloat16* __restrict__ lo, long mkd, long totpad) {
    long i = (long)blockIdx.x * blockDim.x + threadIdx.x;
    if (i >= totpad) return;
    float v = (i < mkd) ? in[i] : 0.f;
    __nv_bfloat16 h = __float2bfloat16(v);
    hi[i] = h;
    lo[i] = __float2bfloat16(v - __bfloat162float(h));
}

// ---------------------------------------------------------------------------
// mma.sync GEMM: C[M,N] = A[M,K] @ W[N,K]^T + bias, optional ReLU.
// A padded hi/lo bf16 [MPAD,K]; W hi/lo bf16 [N,K].
// CTA 128x128, 8 warps (2x4) each 64x32. K-chunk 64, cp.async double buffer.
// Smem tile rows are 128B = 8 x 16B chunks, chunk XOR-swizzled by (row&7).
// Split precision: D += Ahi*Bhi + Alo*Bhi + Ahi*Blo.
// ---------------------------------------------------------------------------
template <int RELU>
__global__ void __launch_bounds__(256, 1)
tgemm_kernel(const __nv_bfloat16* __restrict__ Ahi, const __nv_bfloat16* __restrict__ Alo,
             const __nv_bfloat16* __restrict__ Bhi, const __nv_bfloat16* __restrict__ Blo,
             const float* __restrict__ bias, float* __restrict__ Cout,
             int Mout, int N, int Kd) {
    extern __shared__ char smc[];
    const uint32_t sbase = smem_u32(smc);
    constexpr int TILE = 16384;              // 128 rows x 128 bytes
    const int tid  = threadIdx.x;
    const int warp = tid >> 5, lane = tid & 31;
    const int n0 = blockIdx.x * 128, m0 = blockIdx.y * 128;
    const int wm = (warp >> 2) * 64;         // warp row offset in tile
    const int wn = (warp & 3) * 32;          // warp col offset in tile

    float acc[4][4][4];
#pragma unroll
    for (int i = 0; i < 4; i++)
#pragma unroll
        for (int j = 0; j < 4; j++)
#pragma unroll
            for (int q = 0; q < 4; q++) acc[i][j][q] = 0.f;

    const __nv_bfloat16* srcs[4] = {
        Ahi + (long)m0 * Kd, Alo + (long)m0 * Kd,
        Bhi + (long)n0 * Kd, Blo + (long)n0 * Kd };

    const int nch = Kd >> 6;

    // stage chunk c into buffer b (4 tiles x 1024 16B-chunks, 4 per thread/tile)
    auto stage = [&](int c, int b) {
        const int k0 = c << 6;
        const uint32_t bufb = sbase + b * 4 * TILE;
#pragma unroll
        for (int tI = 0; tI < 4; tI++) {
            const __nv_bfloat16* src = srcs[tI] + k0;
            const uint32_t dstb = bufb + tI * TILE;
#pragma unroll
            for (int i = 0; i < 4; i++) {
                int idx = tid * 4 + i;               // 0..1023
                int r = idx >> 3, ch = idx & 7;
                uint32_t dst = dstb + r * 128 + ((ch ^ (r & 7)) << 4);
                cp_async16(dst, src + (long)r * Kd + ch * 8);
            }
        }
        cp_commit();
    };

    stage(0, 0);

    for (int c = 0; c < nch; c++) {
        const int b = c & 1;
        if (c + 1 < nch) {
            stage(c + 1, b ^ 1);
            asm volatile("cp.async.wait_group 1;" ::: "memory");
        } else {
            asm volatile("cp.async.wait_group 0;" ::: "memory");
        }
        __syncthreads();

        const uint32_t tAhi = sbase + b * 4 * TILE;
        const uint32_t tAlo = tAhi + TILE;
        const uint32_t tBhi = tAhi + 2 * TILE;
        const uint32_t tBlo = tAhi + 3 * TILE;

#pragma unroll
        for (int kk = 0; kk < 64; kk += 16) {
            // A fragments: lane -> row (lane&15), k-half (lane>>4)
            uint32_t ahi[4][4], alo[4][4];
            {
                const int ar = (lane & 15);
                const int ac = (kk >> 3) + (lane >> 4);
#pragma unroll
                for (int mt = 0; mt < 4; mt++) {
                    int r = wm + mt * 16 + ar;
                    uint32_t off = r * 128 + ((ac ^ (r & 7)) << 4);
                    ldm_x4(ahi[mt], tAhi + off);
                    ldm_x4(alo[mt], tAlo + off);
                }
            }
            // B fragments: lanes 0-7 -> n-rows @k0, 8-15 -> @k8
            uint32_t bhi[4][2], blo[4][2];
            {
                const int br = (lane & 7);
                const int bc = (kk >> 3) + ((lane >> 3) & 1);
#pragma unroll
                for (int nt = 0; nt < 4; nt++) {
                    int r = wn + nt * 8 + br;
                    uint32_t off = r * 128 + ((bc ^ (r & 7)) << 4);
                    ldm_x2(bhi[nt], tBhi + off);
                    ldm_x2(blo[nt], tBlo + off);
                }
            }
#pragma unroll
            for (int mt = 0; mt < 4; mt++)
#pragma unroll
                for (int nt = 0; nt < 4; nt++) {
                    mma_bf16(acc[mt][nt], ahi[mt], bhi[nt]);
                    mma_bf16(acc[mt][nt], alo[mt], bhi[nt]);
                    mma_bf16(acc[mt][nt], ahi[mt], blo[nt]);
                }
        }
        __syncthreads();
    }

    // epilogue: c frag -> rows (lane>>2, +8), cols (lane&3)*2 within n8 tile
    const int tq = lane >> 2, tr = lane & 3;
#pragma unroll
    for (int mt = 0; mt < 4; mt++) {
        const int row0 = m0 + wm + mt * 16;
#pragma unroll
        for (int nt = 0; nt < 4; nt++) {
            const int col = n0 + wn + nt * 8 + tr * 2;
            const float2 bv = *(const float2*)(bias + col);
            float* a4 = acc[mt][nt];
            int r1 = row0 + tq, r2 = row0 + tq + 8;
            float2 o1 = { a4[0] + bv.x, a4[1] + bv.y };
            float2 o2 = { a4[2] + bv.x, a4[3] + bv.y };
            if (RELU) {
                o1.x = fmaxf(o1.x, 0.f); o1.y = fmaxf(o1.y, 0.f);
                o2.x = fmaxf(o2.x, 0.f); o2.y = fmaxf(o2.y, 0.f);
            }
            if (r1 < Mout) *(float2*)(Cout + (long)r1 * N + col) = o1;
            if (r2 < Mout) *(float2*)(Cout + (long)r2 * N + col) = o2;
        }
    }
}

// ---------------------------------------------------------------------------
// Depthwise conv along T (K=7, pad=3), adds bias.
// ---------------------------------------------------------------------------
__global__ void dwconv_kernel(const float* __restrict__ x, const float* __restrict__ w,
                              const float* __restrict__ bias, float* __restrict__ y) {
    int bt = blockIdx.x;
    int t  = bt % cfg::T;
    int c  = threadIdx.x;
    const float* xr = x + (long)(bt - t) * cfg::C + c;
    float wr[7];
#pragma unroll
    for (int k = 0; k < 7; k++) wr[k] = w[c * 7 + k];
    float acc = bias[c];
#pragma unroll
    for (int k = 0; k < 7; k++) {
        int tt = t + k - 3;
        if (tt >= 0 && tt < cfg::T) acc += xr[(long)tt * cfg::C] * wr[k];
    }
    y[(long)bt * cfg::C + c] = acc;
}

// ---------------------------------------------------------------------------
// In-place LayerNorm over C=512 per row.
// ---------------------------------------------------------------------------
__global__ void ln_kernel(float* __restrict__ x, const float* __restrict__ g,
                          const float* __restrict__ b) {
    long row = blockIdx.x;
    float* xr = x + row * cfg::C;
    int tid = threadIdx.x;
    float v0 = xr[tid], v1 = xr[tid + 256];
    float s = v0 + v1, ss = v0 * v0 + v1 * v1;
#pragma unroll
    for (int o = 16; o > 0; o >>= 1) {
        s  += __shfl_xor_sync(~0u, s, o);
        ss += __shfl_xor_sync(~0u, ss, o);
    }
    __shared__ float sh_s[8], sh_ss[8];
    int w = tid >> 5, ln = tid & 31;
    if (ln == 0) { sh_s[w] = s; sh_ss[w] = ss; }
    __syncthreads();
    float ts = 0.f, tss = 0.f;
#pragma unroll
    for (int i = 0; i < 8; i++) { ts += sh_s[i]; tss += sh_ss[i]; }
    float mean = ts * (1.f / 512.f);
    float var  = tss * (1.f / 512.f) - mean * mean;
    float rinv = rsqrtf(var + 1e-5f);
    xr[tid]       = (v0 - mean) * rinv * g[tid]       + b[tid];
    xr[tid + 256] = (v1 - mean) * rinv * g[tid + 256] + b[tid + 256];
}

// ---------------------------------------------------------------------------
// Causal flash attention, fp32.
// ---------------------------------------------------------------------------
__global__ void attn_kernel(const float* __restrict__ Q, const float* __restrict__ Kb,
                            const float* __restrict__ V, float* __restrict__ Y) {
    __shared__ float Qs[64][65];
    __shared__ float Ks[32][65];
    __shared__ float Vs[32][65];
    __shared__ float Ps[64][33];
    int qt = blockIdx.x, h = blockIdx.y, bb = blockIdx.z;
    int tid = threadIdx.x;
    int r = tid >> 2, cg = tid & 3;
    const long base = (long)bb * cfg::T * cfg::C + h * cfg::HD;
#pragma unroll
    for (int i = 0; i < 16; i++) {
        int e = tid + i * 256;
        int rr = e >> 6, d = e & 63;
        int iq = qt * 64 + rr;
        Qs[rr][d] = (iq < cfg::T) ? Q[base + (long)iq * cfg::C + d] : 0.f;
    }
    float m = -3e38f, l = 0.f;
    float acc[16];
#pragma unroll
    for (int j = 0; j < 16; j++) acc[j] = 0.f;
    int iq = qt * 64 + r;
    int ktmax = 2 * qt + 1;
    __syncthreads();
    for (int kt = 0; kt <= ktmax; kt++) {
#pragma unroll
        for (int i = 0; i < 8; i++) {
            int e = tid + i * 256;
            int rr = e >> 6, d = e & 63;
            int jg = kt * 32 + rr;
            float kv = 0.f, vv = 0.f;
            if (jg < cfg::T) {
                kv = Kb[base + (long)jg * cfg::C + d];
                vv = V [base + (long)jg * cfg::C + d];
            }
            Ks[rr][d] = kv; Vs[rr][d] = vv;
        }
        __syncthreads();
        float s[8];
#pragma unroll
        for (int j = 0; j < 8; j++) s[j] = 0.f;
#pragma unroll
        for (int d = 0; d < 64; d++) {
            float qd = Qs[r][d];
#pragma unroll
            for (int j = 0; j < 8; j++) s[j] += qd * Ks[cg * 8 + j][d];
        }
        float mloc = -3e38f;
#pragma unroll
        for (int j = 0; j < 8; j++) {
            int jg = kt * 32 + cg * 8 + j;
            s[j] = (jg <= iq && jg < cfg::T) ? s[j] * cfg::SCALE : -1e30f;
            mloc = fmaxf(mloc, s[j]);
        }
        mloc = fmaxf(mloc, __shfl_xor_sync(~0u, mloc, 1));
        mloc = fmaxf(mloc, __shfl_xor_sync(~0u, mloc, 2));
        float mnew = fmaxf(m, mloc);
        float psum = 0.f;
#pragma unroll
        for (int j = 0; j < 8; j++) {
            float p = __expf(s[j] - mnew);
            Ps[r][cg * 8 + j] = p;
            psum += p;
        }
        psum += __shfl_xor_sync(~0u, psum, 1);
        psum += __shfl_xor_sync(~0u, psum, 2);
        float sc = __expf(m - mnew);
        l = l * sc + psum;
        m = mnew;
#pragma unroll
        for (int j = 0; j < 16; j++) acc[j] *= sc;
        __syncthreads();
#pragma unroll
        for (int c = 0; c < 32; c++) {
            float p = Ps[r][c];
#pragma unroll
            for (int j = 0; j < 16; j++) acc[j] += p * Vs[c][cg * 16 + j];
        }
        __syncthreads();
    }
    if (iq < cfg::T) {
        float rl = 1.f / l;
#pragma unroll
        for (int j = 0; j < 16; j++)
            Y[base + (long)iq * cfg::C + cg * 16 + j] = acc[j] * rl;
    }
}

// ---------------------------------------------------------------------------
// Orchestration (graph-capturable)
// ---------------------------------------------------------------------------
extern "C" void kernel_launch(void* const* d_in, const int* in_sizes, int n_in,
                              void* d_out, int out_size) {
    using namespace cfg;
    const float* x     = (const float*)d_in[0];
    const float* dw_w  = (const float*)d_in[1];
    const float* dw_b  = (const float*)d_in[2];
    const float* pw_w  = (const float*)d_in[3];
    const float* pw_b  = (const float*)d_in[4];
    const float* cln_g = (const float*)d_in[5];
    const float* cln_b = (const float*)d_in[6];
    const float* wq = (const float*)d_in[7];  const float* bq = (const float*)d_in[8];
    const float* wk = (const float*)d_in[9];  const float* bk = (const float*)d_in[10];
    const float* wv = (const float*)d_in[11]; const float* bv = (const float*)d_in[12];
    const float* wo = (const float*)d_in[13]; const float* bo = (const float*)d_in[14];
    const float* aln_g = (const float*)d_in[15]; const float* aln_b = (const float*)d_in[16];
    const float* w1 = (const float*)d_in[17]; const float* b1 = (const float*)d_in[18];
    const float* w2 = (const float*)d_in[19]; const float* b2 = (const float*)d_in[20];
    const float* fln_g = (const float*)d_in[21]; const float* fln_b = (const float*)d_in[22];
    float* out = (float*)d_out;

    float *t0, *t1, *qb, *kb, *vb, *hid;
    __nv_bfloat16 *ahi, *alo, *whi, *wlo;
    cudaGetSymbolAddress((void**)&t0,  g_t0);
    cudaGetSymbolAddress((void**)&t1,  g_t1);
    cudaGetSymbolAddress((void**)&qb,  g_q);
    cudaGetSymbolAddress((void**)&kb,  g_k);
    cudaGetSymbolAddress((void**)&vb,  g_v);
    cudaGetSymbolAddress((void**)&hid, g_hid);
    cudaGetSymbolAddress((void**)&ahi, g_ahi);
    cudaGetSymbolAddress((void**)&alo, g_alo);
    cudaGetSymbolAddress((void**)&whi, g_whi);
    cudaGetSymbolAddress((void**)&wlo, g_wlo);

    constexpr int SMEM = 2 * 4 * 16384;   // 131,072 bytes (double buffer, 4 tiles)
    cudaFuncSetAttribute(tgemm_kernel<0>, cudaFuncAttributeMaxDynamicSharedMemorySize, SMEM);
    cudaFuncSetAttribute(tgemm_kernel<1>, cudaFuncAttributeMaxDynamicSharedMemorySize, SMEM);

    // ---- convert all weights to hi/lo bf16 ----
    auto cvtw = [&](const float* src, long off, long len) {
        cvt_w_kernel<<<(int)((len + 255) / 256), 256>>>(src, whi + off, wlo + off, len);
    };
    cvtw(pw_w, OFF_PW, LEN_PW);
    cvtw(wq,   OFF_WQ, LEN_W);
    cvtw(wk,   OFF_WK, LEN_W);
    cvtw(wv,   OFF_WV, LEN_W);
    cvtw(wo,   OFF_WO, LEN_W);
    cvtw(w1,   OFF_W1, LEN_W1);
    cvtw(w2,   OFF_W2, LEN_W2);

    auto cvta = [&](const float* src, int Kd) {
        long mkd = (long)BT * Kd, tot = (long)MPAD * Kd;
        cvt_act_kernel<<<(int)((tot + 255) / 256), 256>>>(src, ahi, alo, mkd, tot);
    };

    dim3 gCC(C / 128, MPAD / 128);      // N=512 output tiles
    dim3 gCH(HID / 128, MPAD / 128);    // N=2048 output tiles

    const float* cur = x;
    for (int l = 0; l < L; l++) {
        // ---- conv blocks ----
        for (int nc = 0; nc < NC; nc++) {
            const float* cin = (nc == 0) ? cur : t1;
            long idx = (long)(l * NC + nc);
            dwconv_kernel<<<BT, C>>>(cin, dw_w + idx * C * K, dw_b + idx * C, t0);
            cvta(t0, C);
            tgemm_kernel<0><<<gCC, 256, SMEM>>>(ahi, alo, whi + OFF_PW + idx * C * C,
                wlo + OFF_PW + idx * C * C, pw_b + idx * C, t1, BT, C, C);
            ln_kernel<<<BT, 256>>>(t1, cln_g + idx * C, cln_b + idx * C);
        }
        // ---- attention ----
        long lw = (long)l * C * C;
        cvta(t1, C);
        tgemm_kernel<0><<<gCC, 256, SMEM>>>(ahi, alo, whi + OFF_WQ + lw, wlo + OFF_WQ + lw,
                                            bq + (long)l * C, qb, BT, C, C);
        tgemm_kernel<0><<<gCC, 256, SMEM>>>(ahi, alo, whi + OFF_WK + lw, wlo + OFF_WK + lw,
                                            bk + (long)l * C, kb, BT, C, C);
        tgemm_kernel<0><<<gCC, 256, SMEM>>>(ahi, alo, whi + OFF_WV + lw, wlo + OFF_WV + lw,
                                            bv + (long)l * C, vb, BT, C, C);
        attn_kernel<<<dim3(8, NH, B), 256>>>(qb, kb, vb, t0);
        cvta(t0, C);
        tgemm_kernel<0><<<gCC, 256, SMEM>>>(ahi, alo, whi + OFF_WO + lw, wlo + OFF_WO + lw,
                                            bo + (long)l * C, t1, BT, C, C);
        ln_kernel<<<BT, 256>>>(t1, aln_g + (long)l * C, aln_b + (long)l * C);
        // ---- FFN ----
        cvta(t1, C);
        tgemm_kernel<1><<<gCH, 256, SMEM>>>(ahi, alo, whi + OFF_W1 + (long)l * HID * C,
            wlo + OFF_W1 + (long)l * HID * C, b1 + (long)l * HID, hid, BT, HID, C);
        cvta(hid, HID);
        float* outl = out + (long)l * BTC;
        tgemm_kernel<0><<<gCC, 256, SMEM>>>(ahi, alo, whi + OFF_W2 + (long)l * C * HID,
            wlo + OFF_W2 + (long)l * C * HID, b2 + (long)l * C, outl, BT, C, HID);
        ln_kernel<<<BT, 256>>>(outl, fln_g + (long)l * C, fln_b + (long)l * C);
        cur = outl;
    }
}

// round 9
// speedup vs baseline: 3.0770x; 1.6081x over previous
#include <cuda_runtime.h>
#include <cuda_bf16.h>
#include <cstdint>
#include <math.h>

using std::uint32_t;
using std::uint64_t;

namespace cfg {
constexpr int B = 16, T = 500, C = 512, K = 7, NH = 8, HD = 64, HID = 2048, L = 3, NC = 2;
constexpr int BT = B * T;                  // 8000
constexpr int MPAD = 8064;                 // 63 * 128
constexpr long BTC = (long)BT * C;
constexpr float SCALE = 0.125f;
constexpr long OFF_PW = 0;
constexpr long LEN_PW = (long)L * NC * C * C;
constexpr long OFF_WQ = OFF_PW + LEN_PW;
constexpr long LEN_W  = (long)L * C * C;
constexpr long OFF_WK = OFF_WQ + LEN_W;
constexpr long OFF_WV = OFF_WK + LEN_W;
constexpr long OFF_WO = OFF_WV + LEN_W;
constexpr long OFF_W1 = OFF_WO + LEN_W;
constexpr long LEN_W1 = (long)L * HID * C;
constexpr long OFF_W2 = OFF_W1 + LEN_W1;
constexpr long LEN_W2 = (long)L * C * HID;
constexpr long WTOT   = OFF_W2 + LEN_W2;
}

// ---------------------------------------------------------------------------
// Scratch (device globals; no allocation allowed)
// ---------------------------------------------------------------------------
__device__ float g_t1[cfg::BT * cfg::C];
__device__ __nv_bfloat16 g_a512h[(long)cfg::MPAD * cfg::C];
__device__ __nv_bfloat16 g_a512l[(long)cfg::MPAD * cfg::C];
__device__ __nv_bfloat16 g_a2kh [(long)cfg::MPAD * cfg::HID];
__device__ __nv_bfloat16 g_a2kl [(long)cfg::MPAD * cfg::HID];
__device__ __nv_bfloat16 g_qh[(long)cfg::BT * cfg::C];
__device__ __nv_bfloat16 g_ql[(long)cfg::BT * cfg::C];
__device__ __nv_bfloat16 g_kh[(long)cfg::BT * cfg::C];
__device__ __nv_bfloat16 g_kl[(long)cfg::BT * cfg::C];
__device__ __nv_bfloat16 g_vh[(long)cfg::BT * cfg::C];
__device__ __nv_bfloat16 g_vl[(long)cfg::BT * cfg::C];
__device__ __nv_bfloat16 g_whi[cfg::WTOT];
__device__ __nv_bfloat16 g_wlo[cfg::WTOT];

// ---------------------------------------------------------------------------
// PTX helpers (plain sm_80+ only; compute_103 rejects the 'a'-suffix ISA)
// ---------------------------------------------------------------------------
__device__ __forceinline__ uint32_t smem_u32(const void* p) {
    uint32_t a;
    asm("{ .reg .u64 t; cvta.to.shared.u64 t, %1; cvt.u32.u64 %0, t; }" : "=r"(a) : "l"(p));
    return a;
}
__device__ __forceinline__ void cp_async16(uint32_t dst, const void* src) {
    asm volatile("cp.async.ca.shared.global [%0], [%1], 16;" :: "r"(dst), "l"(src));
}
__device__ __forceinline__ void cp_commit() {
    asm volatile("cp.async.commit_group;" ::: "memory");
}
__device__ __forceinline__ void ldm_x4(uint32_t* a, uint32_t addr) {
    asm volatile("ldmatrix.sync.aligned.m8n8.x4.shared.b16 {%0,%1,%2,%3}, [%4];"
                 : "=r"(a[0]), "=r"(a[1]), "=r"(a[2]), "=r"(a[3]) : "r"(addr));
}
__device__ __forceinline__ void ldm_x2(uint32_t* b, uint32_t addr) {
    asm volatile("ldmatrix.sync.aligned.m8n8.x2.shared.b16 {%0,%1}, [%2];"
                 : "=r"(b[0]), "=r"(b[1]) : "r"(addr));
}
__device__ __forceinline__ void mma_bf16(float* d, const uint32_t* a, const uint32_t* b) {
    asm volatile(
        "mma.sync.aligned.m16n8k16.row.col.f32.bf16.bf16.f32 "
        "{%0,%1,%2,%3},{%4,%5,%6,%7},{%8,%9},{%0,%1,%2,%3};"
        : "+f"(d[0]), "+f"(d[1]), "+f"(d[2]), "+f"(d[3])
        : "r"(a[0]), "r"(a[1]), "r"(a[2]), "r"(a[3]), "r"(b[0]), "r"(b[1]));
}
__device__ __forceinline__ uint32_t pack_bf16(__nv_bfloat16 a, __nv_bfloat16 b) {
    __nv_bfloat162 t(a, b);            // a = low half
    return *reinterpret_cast<uint32_t*>(&t);
}
// split a pair of fp32 into packed hi/lo bf16 pairs
__device__ __forceinline__ void split2(float a, float b, uint32_t& hi, uint32_t& lo) {
    __nv_bfloat16 ah = __float2bfloat16(a), bh = __float2bfloat16(b);
    float ar = a - __bfloat162float(ah), br = b - __bfloat162float(bh);
    hi = pack_bf16(ah, bh);
    lo = pack_bf16(__float2bfloat16(ar), __float2bfloat16(br));
}

// ---------------------------------------------------------------------------
// fp32 -> (hi, lo) bf16 weight converter
// ---------------------------------------------------------------------------
__global__ void cvt_w_kernel(const float* __restrict__ in, __nv_bfloat16* __restrict__ hi,
                             __nv_bfloat16* __restrict__ lo, long n) {
    long i = (long)blockIdx.x * blockDim.x + threadIdx.x;
    if (i >= n) return;
    float v = in[i];
    __nv_bfloat16 h = __float2bfloat16(v);
    hi[i] = h;
    lo[i] = __float2bfloat16(v - __bfloat162float(h));
}

// zero the pad rows (8000..8063) of both activation layouts; runs once per launch
__global__ void zero_pad_kernel(__nv_bfloat16* a5h, __nv_bfloat16* a5l,
                                __nv_bfloat16* a2h, __nv_bfloat16* a2l) {
    int i = blockIdx.x * blockDim.x + threadIdx.x;
    if (i < 64 * 512) {
        long o = (long)8000 * 512 + i;
        a5h[o] = __nv_bfloat16(0.f); a5l[o] = __nv_bfloat16(0.f);
    }
    if (i < 64 * 2048) {
        long o = (long)8000 * 2048 + i;
        a2h[o] = __nv_bfloat16(0.f); a2l[o] = __nv_bfloat16(0.f);
    }
}

// ---------------------------------------------------------------------------
// mma.sync GEMM: C[M,N] = A[M,K] @ W[N,K]^T + bias.
// RELU optional; HILO: write split-bf16 (Ohi/Olo) instead of fp32 Cout.
// ---------------------------------------------------------------------------
template <int RELU, int HILO>
__global__ void __launch_bounds__(256, 1)
tgemm_kernel(const __nv_bfloat16* __restrict__ Ahi, const __nv_bfloat16* __restrict__ Alo,
             const __nv_bfloat16* __restrict__ Bhi, const __nv_bfloat16* __restrict__ Blo,
             const float* __restrict__ bias, float* __restrict__ Cout,
             __nv_bfloat16* __restrict__ Ohi, __nv_bfloat16* __restrict__ Olo,
             int Mout, int N, int Kd) {
    extern __shared__ char smc[];
    const uint32_t sbase = smem_u32(smc);
    constexpr int TILE = 16384;
    const int tid  = threadIdx.x;
    const int warp = tid >> 5, lane = tid & 31;
    const int n0 = blockIdx.x * 128, m0 = blockIdx.y * 128;
    const int wm = (warp >> 2) * 64;
    const int wn = (warp & 3) * 32;

    float acc[4][4][4];
#pragma unroll
    for (int i = 0; i < 4; i++)
#pragma unroll
        for (int j = 0; j < 4; j++)
#pragma unroll
            for (int q = 0; q < 4; q++) acc[i][j][q] = 0.f;

    const __nv_bfloat16* srcs[4] = {
        Ahi + (long)m0 * Kd, Alo + (long)m0 * Kd,
        Bhi + (long)n0 * Kd, Blo + (long)n0 * Kd };
    const int nch = Kd >> 6;

    auto stage = [&](int c, int b) {
        const int k0 = c << 6;
        const uint32_t bufb = sbase + b * 4 * TILE;
#pragma unroll
        for (int tI = 0; tI < 4; tI++) {
            const __nv_bfloat16* src = srcs[tI] + k0;
            const uint32_t dstb = bufb + tI * TILE;
#pragma unroll
            for (int i = 0; i < 4; i++) {
                int idx = tid * 4 + i;
                int r = idx >> 3, ch = idx & 7;
                uint32_t dst = dstb + r * 128 + ((ch ^ (r & 7)) << 4);
                cp_async16(dst, src + (long)r * Kd + ch * 8);
            }
        }
        cp_commit();
    };

    stage(0, 0);
    for (int c = 0; c < nch; c++) {
        const int b = c & 1;
        if (c + 1 < nch) {
            stage(c + 1, b ^ 1);
            asm volatile("cp.async.wait_group 1;" ::: "memory");
        } else {
            asm volatile("cp.async.wait_group 0;" ::: "memory");
        }
        __syncthreads();

        const uint32_t tAhi = sbase + b * 4 * TILE;
        const uint32_t tAlo = tAhi + TILE;
        const uint32_t tBhi = tAhi + 2 * TILE;
        const uint32_t tBlo = tAhi + 3 * TILE;

#pragma unroll
        for (int kk = 0; kk < 64; kk += 16) {
            uint32_t ahi[4][4], alo[4][4];
            {
                const int ar = (lane & 15);
                const int ac = (kk >> 3) + (lane >> 4);
#pragma unroll
                for (int mt = 0; mt < 4; mt++) {
                    int r = wm + mt * 16 + ar;
                    uint32_t off = r * 128 + ((ac ^ (r & 7)) << 4);
                    ldm_x4(ahi[mt], tAhi + off);
                    ldm_x4(alo[mt], tAlo + off);
                }
            }
            uint32_t bhi[4][2], blo[4][2];
            {
                const int br = (lane & 7);
                const int bc = (kk >> 3) + ((lane >> 3) & 1);
#pragma unroll
                for (int nt = 0; nt < 4; nt++) {
                    int r = wn + nt * 8 + br;
                    uint32_t off = r * 128 + ((bc ^ (r & 7)) << 4);
                    ldm_x2(bhi[nt], tBhi + off);
                    ldm_x2(blo[nt], tBlo + off);
                }
            }
#pragma unroll
            for (int mt = 0; mt < 4; mt++)
#pragma unroll
                for (int nt = 0; nt < 4; nt++) {
                    mma_bf16(acc[mt][nt], ahi[mt], bhi[nt]);
                    mma_bf16(acc[mt][nt], alo[mt], bhi[nt]);
                    mma_bf16(acc[mt][nt], ahi[mt], blo[nt]);
                }
        }
        __syncthreads();
    }

    const int tq = lane >> 2, tr = lane & 3;
#pragma unroll
    for (int mt = 0; mt < 4; mt++) {
        const int row0 = m0 + wm + mt * 16;
#pragma unroll
        for (int nt = 0; nt < 4; nt++) {
            const int col = n0 + wn + nt * 8 + tr * 2;
            const float2 bv = *(const float2*)(bias + col);
            float* a4 = acc[mt][nt];
            int r1 = row0 + tq, r2 = row0 + tq + 8;
            float o1x = a4[0] + bv.x, o1y = a4[1] + bv.y;
            float o2x = a4[2] + bv.x, o2y = a4[3] + bv.y;
            if (RELU) {
                o1x = fmaxf(o1x, 0.f); o1y = fmaxf(o1y, 0.f);
                o2x = fmaxf(o2x, 0.f); o2y = fmaxf(o2y, 0.f);
            }
            if (r1 < Mout) {
                if (HILO) {
                    uint32_t h, l;
                    split2(o1x, o1y, h, l);
                    *(uint32_t*)(Ohi + (long)r1 * N + col) = h;
                    *(uint32_t*)(Olo + (long)r1 * N + col) = l;
                } else {
                    float2 o = {o1x, o1y};
                    *(float2*)(Cout + (long)r1 * N + col) = o;
                }
            }
            if (r2 < Mout) {
                if (HILO) {
                    uint32_t h, l;
                    split2(o2x, o2y, h, l);
                    *(uint32_t*)(Ohi + (long)r2 * N + col) = h;
                    *(uint32_t*)(Olo + (long)r2 * N + col) = l;
                } else {
                    float2 o = {o2x, o2y};
                    *(float2*)(Cout + (long)r2 * N + col) = o;
                }
            }
        }
    }
}

// ---------------------------------------------------------------------------
// Depthwise conv along T (K=7, pad=3) + bias; writes split-bf16 hi/lo.
// ---------------------------------------------------------------------------
__global__ void dwconv_kernel(const float* __restrict__ x, const float* __restrict__ w,
                              const float* __restrict__ bias,
                              __nv_bfloat16* __restrict__ oh, __nv_bfloat16* __restrict__ ol) {
    int bt = blockIdx.x;
    int t  = bt % cfg::T;
    int c  = threadIdx.x;
    const float* xr = x + (long)(bt - t) * cfg::C + c;
    float wr[7];
#pragma unroll
    for (int k = 0; k < 7; k++) wr[k] = w[c * 7 + k];
    float acc = bias[c];
#pragma unroll
    for (int k = 0; k < 7; k++) {
        int tt = t + k - 3;
        if (tt >= 0 && tt < cfg::T) acc += xr[(long)tt * cfg::C] * wr[k];
    }
    __nv_bfloat16 h = __float2bfloat16(acc);
    oh[(long)bt * cfg::C + c] = h;
    ol[(long)bt * cfg::C + c] = __float2bfloat16(acc - __bfloat162float(h));
}

// ---------------------------------------------------------------------------
// LayerNorm over C=512. MODE 0: fp32 in place. MODE 2: split-bf16 out only.
// ---------------------------------------------------------------------------
template <int MODE>
__global__ void ln_kernel(float* __restrict__ x, const float* __restrict__ g,
                          const float* __restrict__ b,
                          __nv_bfloat16* __restrict__ oh, __nv_bfloat16* __restrict__ ol) {
    long row = blockIdx.x;
    float* xr = x + row * cfg::C;
    int tid = threadIdx.x;
    float v0 = xr[tid], v1 = xr[tid + 256];
    float s = v0 + v1, ss = v0 * v0 + v1 * v1;
#pragma unroll
    for (int o = 16; o > 0; o >>= 1) {
        s  += __shfl_xor_sync(~0u, s, o);
        ss += __shfl_xor_sync(~0u, ss, o);
    }
    __shared__ float sh_s[8], sh_ss[8];
    int w = tid >> 5, ln = tid & 31;
    if (ln == 0) { sh_s[w] = s; sh_ss[w] = ss; }
    __syncthreads();
    float ts = 0.f, tss = 0.f;
#pragma unroll
    for (int i = 0; i < 8; i++) { ts += sh_s[i]; tss += sh_ss[i]; }
    float mean = ts * (1.f / 512.f);
    float var  = tss * (1.f / 512.f) - mean * mean;
    float rinv = rsqrtf(var + 1e-5f);
    float o0 = (v0 - mean) * rinv * g[tid]       + b[tid];
    float o1 = (v1 - mean) * rinv * g[tid + 256] + b[tid + 256];
    if (MODE == 0) {
        xr[tid] = o0; xr[tid + 256] = o1;
    } else {
        __nv_bfloat16 h0 = __float2bfloat16(o0), h1 = __float2bfloat16(o1);
        oh[row * cfg::C + tid]       = h0;
        oh[row * cfg::C + tid + 256] = h1;
        ol[row * cfg::C + tid]       = __float2bfloat16(o0 - __bfloat162float(h0));
        ol[row * cfg::C + tid + 256] = __float2bfloat16(o1 - __bfloat162float(h1));
    }
}

// ---------------------------------------------------------------------------
// Tensor-core causal flash attention, 3-pass split-bf16 for QK^T and PV.
// Grid (8 qtiles, NH, B), 128 threads (4 warps x m16 q-rows).
// smem tiles [64][72] bf16: Qhi,Qlo (q rows x hd), Khi,Klo (key x hd),
// Vthi,Vtlo (hd x key, explicitly transposed at staging).
// Output: split-bf16 hi/lo (feeds the WO GEMM directly).
// ---------------------------------------------------------------------------
__global__ void __launch_bounds__(128)
attn_kernel(const __nv_bfloat16* __restrict__ qh, const __nv_bfloat16* __restrict__ ql,
            const __nv_bfloat16* __restrict__ kh, const __nv_bfloat16* __restrict__ kl,
            const __nv_bfloat16* __restrict__ vh, const __nv_bfloat16* __restrict__ vl,
            __nv_bfloat16* __restrict__ oh, __nv_bfloat16* __restrict__ ol) {
    extern __shared__ char smc[];
    const uint32_t sbase = smem_u32(smc);
    constexpr int TB = 64 * 72 * 2;   // 9216 bytes per tile
    const uint32_t QH = 0, QL = TB, KH = 2 * TB, KL = 3 * TB, VH = 4 * TB, VL = 5 * TB;
    __nv_bfloat16* sp = (__nv_bfloat16*)smc;

    const int qt = blockIdx.x, hh = blockIdx.y, bb = blockIdx.z;
    const int tid = threadIdx.x;
    const int warp = tid >> 5, lane = tid & 31;
    const long brow = (long)bb * cfg::T;
    const int hc = hh * cfg::HD;

    // stage Q tile (hi/lo), zero-filled beyond T
#pragma unroll
    for (int i = 0; i < 16; i++) {
        int idx = tid + i * 128;          // 0..2047 bf162 units
        int rr = idx >> 5, d2 = idx & 31;
        int iq = qt * 64 + rr;
        uint32_t a = 0, c = 0;
        if (iq < cfg::T) {
            a = *(const uint32_t*)(qh + (brow + iq) * cfg::C + hc + d2 * 2);
            c = *(const uint32_t*)(ql + (brow + iq) * cfg::C + hc + d2 * 2);
        }
        *(uint32_t*)(smc + QH + rr * 144 + d2 * 4) = a;
        *(uint32_t*)(smc + QL + rr * 144 + d2 * 4) = c;
    }

    float m0 = -1e30f, m1 = -1e30f, l0 = 0.f, l1 = 0.f;
    float O[8][4];
#pragma unroll
    for (int i = 0; i < 8; i++)
#pragma unroll
        for (int j = 0; j < 4; j++) O[i][j] = 0.f;

    const int wm = warp * 16;
    const int rowg0 = qt * 64 + wm + (lane >> 2);
    const int rowg1 = rowg0 + 8;

    for (int ch = 0; ch <= qt; ch++) {
        const int kv0 = ch * 64;
        __syncthreads();   // previous chunk's K/V reads done before overwrite
#pragma unroll
        for (int i = 0; i < 16; i++) {
            int idx = tid + i * 128;
            int rr = idx >> 5, d2 = idx & 31;
            int jg = kv0 + rr;
            uint32_t ka = 0, kc = 0, va = 0, vc = 0;
            if (jg < cfg::T) {
                ka = *(const uint32_t*)(kh + (brow + jg) * cfg::C + hc + d2 * 2);
                kc = *(const uint32_t*)(kl + (brow + jg) * cfg::C + hc + d2 * 2);
                va = *(const uint32_t*)(vh + (brow + jg) * cfg::C + hc + d2 * 2);
                vc = *(const uint32_t*)(vl + (brow + jg) * cfg::C + hc + d2 * 2);
            }
            *(uint32_t*)(smc + KH + rr * 144 + d2 * 4) = ka;
            *(uint32_t*)(smc + KL + rr * 144 + d2 * 4) = kc;
            // transpose V: Vt[d][key]
            __nv_bfloat162 tv = *reinterpret_cast<__nv_bfloat162*>(&va);
            __nv_bfloat162 tl = *reinterpret_cast<__nv_bfloat162*>(&vc);
            sp[(VH >> 1) + (2 * d2) * 72 + rr]     = tv.x;
            sp[(VH >> 1) + (2 * d2 + 1) * 72 + rr] = tv.y;
            sp[(VL >> 1) + (2 * d2) * 72 + rr]     = tl.x;
            sp[(VL >> 1) + (2 * d2 + 1) * 72 + rr] = tl.y;
        }
        __syncthreads();

        // scores S = Q K^T (3-pass split)
        float S[8][4];
#pragma unroll
        for (int i = 0; i < 8; i++)
#pragma unroll
            for (int j = 0; j < 4; j++) S[i][j] = 0.f;
#pragma unroll
        for (int kk = 0; kk < 64; kk += 16) {
            uint32_t qa_h[4], qa_l[4];
            {
                int r = wm + (lane & 15);
                uint32_t off = r * 144 + ((kk >> 3) + (lane >> 4)) * 16;
                ldm_x4(qa_h, sbase + QH + off);
                ldm_x4(qa_l, sbase + QL + off);
            }
#pragma unroll
            for (int nt = 0; nt < 8; nt++) {
                uint32_t kb_h[2], kb_l[2];
                int r = nt * 8 + (lane & 7);
                uint32_t off = r * 144 + ((kk >> 3) + ((lane >> 3) & 1)) * 16;
                ldm_x2(kb_h, sbase + KH + off);
                ldm_x2(kb_l, sbase + KL + off);
                mma_bf16(S[nt], qa_h, kb_h);
                mma_bf16(S[nt], qa_l, kb_h);
                mma_bf16(S[nt], qa_h, kb_l);
            }
        }
        // scale + causal/bounds mask
        const int colb = kv0 + (lane & 3) * 2;
#pragma unroll
        for (int nt = 0; nt < 8; nt++) {
            int c0 = colb + nt * 8, c1 = c0 + 1;
            S[nt][0] = (c0 <= rowg0 && c0 < cfg::T) ? S[nt][0] * cfg::SCALE : -1e30f;
            S[nt][1] = (c1 <= rowg0 && c1 < cfg::T) ? S[nt][1] * cfg::SCALE : -1e30f;
            S[nt][2] = (c0 <= rowg1 && c0 < cfg::T) ? S[nt][2] * cfg::SCALE : -1e30f;
            S[nt][3] = (c1 <= rowg1 && c1 < cfg::T) ? S[nt][3] * cfg::SCALE : -1e30f;
        }
        // online softmax
        float mx0 = -1e30f, mx1 = -1e30f;
#pragma unroll
        for (int nt = 0; nt < 8; nt++) {
            mx0 = fmaxf(mx0, fmaxf(S[nt][0], S[nt][1]));
            mx1 = fmaxf(mx1, fmaxf(S[nt][2], S[nt][3]));
        }
        mx0 = fmaxf(mx0, __shfl_xor_sync(~0u, mx0, 1));
        mx0 = fmaxf(mx0, __shfl_xor_sync(~0u, mx0, 2));
        mx1 = fmaxf(mx1, __shfl_xor_sync(~0u, mx1, 1));
        mx1 = fmaxf(mx1, __shfl_xor_sync(~0u, mx1, 2));
        float mn0 = fmaxf(m0, mx0), mn1 = fmaxf(m1, mx1);
        float cr0 = __expf(m0 - mn0), cr1 = __expf(m1 - mn1);
        float ps0 = 0.f, ps1 = 0.f;
#pragma unroll
        for (int nt = 0; nt < 8; nt++) {
            S[nt][0] = __expf(S[nt][0] - mn0); ps0 += S[nt][0];
            S[nt][1] = __expf(S[nt][1] - mn0); ps0 += S[nt][1];
            S[nt][2] = __expf(S[nt][2] - mn1); ps1 += S[nt][2];
            S[nt][3] = __expf(S[nt][3] - mn1); ps1 += S[nt][3];
        }
        ps0 += __shfl_xor_sync(~0u, ps0, 1); ps0 += __shfl_xor_sync(~0u, ps0, 2);
        ps1 += __shfl_xor_sync(~0u, ps1, 1); ps1 += __shfl_xor_sync(~0u, ps1, 2);
        l0 = l0 * cr0 + ps0; l1 = l1 * cr1 + ps1;
        m0 = mn0; m1 = mn1;
#pragma unroll
        for (int nt = 0; nt < 8; nt++) {
            O[nt][0] *= cr0; O[nt][1] *= cr0;
            O[nt][2] *= cr1; O[nt][3] *= cr1;
        }
        // PV (3-pass split); P a-frags built from score c-frags
#pragma unroll
        for (int ks = 0; ks < 4; ks++) {
            uint32_t pa_h[4], pa_l[4];
            split2(S[2 * ks][0],     S[2 * ks][1],     pa_h[0], pa_l[0]);
            split2(S[2 * ks][2],     S[2 * ks][3],     pa_h[1], pa_l[1]);
            split2(S[2 * ks + 1][0], S[2 * ks + 1][1], pa_h[2], pa_l[2]);
            split2(S[2 * ks + 1][2], S[2 * ks + 1][3], pa_h[3], pa_l[3]);
#pragma unroll
            for (int nt2 = 0; nt2 < 8; nt2++) {
                uint32_t vb_h[2], vb_l[2];
                int r = nt2 * 8 + (lane & 7);
                uint32_t off = r * 144 + (ks * 2 + ((lane >> 3) & 1)) * 16;
                ldm_x2(vb_h, sbase + VH + off);
                ldm_x2(vb_l, sbase + VL + off);
                mma_bf16(O[nt2], pa_h, vb_h);
                mma_bf16(O[nt2], pa_l, vb_h);
                mma_bf16(O[nt2], pa_h, vb_l);
            }
        }
    }

    // normalize + split-bf16 store
    float rl0 = 1.f / l0, rl1 = 1.f / l1;
    const int iq0 = rowg0, iq1 = rowg1;
#pragma unroll
    for (int nt2 = 0; nt2 < 8; nt2++) {
        int col = hc + nt2 * 8 + (lane & 3) * 2;
        if (iq0 < cfg::T) {
            uint32_t h, l;
            split2(O[nt2][0] * rl0, O[nt2][1] * rl0, h, l);
            *(uint32_t*)(oh + (brow + iq0) * cfg::C + col) = h;
            *(uint32_t*)(ol + (brow + iq0) * cfg::C + col) = l;
        }
        if (iq1 < cfg::T) {
            uint32_t h, l;
            split2(O[nt2][2] * rl1, O[nt2][3] * rl1, h, l);
            *(uint32_t*)(oh + (brow + iq1) * cfg::C + col) = h;
            *(uint32_t*)(ol + (brow + iq1) * cfg::C + col) = l;
        }
    }
}

// ---------------------------------------------------------------------------
// Orchestration (graph-capturable)
// ---------------------------------------------------------------------------
extern "C" void kernel_launch(void* const* d_in, const int* in_sizes, int n_in,
                              void* d_out, int out_size) {
    using namespace cfg;
    const float* x     = (const float*)d_in[0];
    const float* dw_w  = (const float*)d_in[1];
    const float* dw_b  = (const float*)d_in[2];
    const float* pw_w  = (const float*)d_in[3];
    const float* pw_b  = (const float*)d_in[4];
    const float* cln_g = (const float*)d_in[5];
    const float* cln_b = (const float*)d_in[6];
    const float* wq = (const float*)d_in[7];  const float* bq = (const float*)d_in[8];
    const float* wk = (const float*)d_in[9];  const float* bk = (const float*)d_in[10];
    const float* wv = (const float*)d_in[11]; const float* bv = (const float*)d_in[12];
    const float* wo = (const float*)d_in[13]; const float* bo = (const float*)d_in[14];
    const float* aln_g = (const float*)d_in[15]; const float* aln_b = (const float*)d_in[16];
    const float* w1 = (const float*)d_in[17]; const float* b1 = (const float*)d_in[18];
    const float* w2 = (const float*)d_in[19]; const float* b2 = (const float*)d_in[20];
    const float* fln_g = (const float*)d_in[21]; const float* fln_b = (const float*)d_in[22];
    float* out = (float*)d_out;

    float* t1;
    __nv_bfloat16 *a5h, *a5l, *a2h, *a2l, *qh, *ql, *kh, *kl, *vh, *vl, *whi, *wlo;
    cudaGetSymbolAddress((void**)&t1,  g_t1);
    cudaGetSymbolAddress((void**)&a5h, g_a512h);
    cudaGetSymbolAddress((void**)&a5l, g_a512l);
    cudaGetSymbolAddress((void**)&a2h, g_a2kh);
    cudaGetSymbolAddress((void**)&a2l, g_a2kl);
    cudaGetSymbolAddress((void**)&qh,  g_qh);
    cudaGetSymbolAddress((void**)&ql,  g_ql);
    cudaGetSymbolAddress((void**)&kh,  g_kh);
    cudaGetSymbolAddress((void**)&kl,  g_kl);
    cudaGetSymbolAddress((void**)&vh,  g_vh);
    cudaGetSymbolAddress((void**)&vl,  g_vl);
    cudaGetSymbolAddress((void**)&whi, g_whi);
    cudaGetSymbolAddress((void**)&wlo, g_wlo);

    constexpr int SMEM  = 2 * 4 * 16384;    // tgemm: 131,072 B
    constexpr int ASMEM = 6 * 64 * 72 * 2;  // attn:   55,296 B
    cudaFuncSetAttribute(tgemm_kernel<0,0>, cudaFuncAttributeMaxDynamicSharedMemorySize, SMEM);
    cudaFuncSetAttribute(tgemm_kernel<0,1>, cudaFuncAttributeMaxDynamicSharedMemorySize, SMEM);
    cudaFuncSetAttribute(tgemm_kernel<1,1>, cudaFuncAttributeMaxDynamicSharedMemorySize, SMEM);
    cudaFuncSetAttribute(attn_kernel,       cudaFuncAttributeMaxDynamicSharedMemorySize, ASMEM);

    // weights -> hi/lo bf16 ; pad rows -> zero
    auto cvtw = [&](const float* src, long off, long len) {
        cvt_w_kernel<<<(int)((len + 255) / 256), 256>>>(src, whi + off, wlo + off, len);
    };
    cvtw(pw_w, OFF_PW, LEN_PW);
    cvtw(wq,   OFF_WQ, LEN_W);
    cvtw(wk,   OFF_WK, LEN_W);
    cvtw(wv,   OFF_WV, LEN_W);
    cvtw(wo,   OFF_WO, LEN_W);
    cvtw(w1,   OFF_W1, LEN_W1);
    cvtw(w2,   OFF_W2, LEN_W2);
    zero_pad_kernel<<<(64 * 2048 + 255) / 256, 256>>>(a5h, a5l, a2h, a2l);

    dim3 gCC(C / 128, MPAD / 128);
    dim3 gCH(HID / 128, MPAD / 128);
    float* nullf = nullptr;
    __nv_bfloat16* nullb = nullptr;

    const float* cur = x;
    for (int l = 0; l < L; l++) {
        // ---- conv block 1: dwconv -> pw GEMM -> LN(fp32, in place) ----
        long i0 = (long)(l * NC + 0);
        dwconv_kernel<<<BT, C>>>(cur, dw_w + i0 * C * K, dw_b + i0 * C, a5h, a5l);
        tgemm_kernel<0,0><<<gCC, 256, SMEM>>>(a5h, a5l, whi + OFF_PW + i0 * C * C,
            wlo + OFF_PW + i0 * C * C, pw_b + i0 * C, t1, nullb, nullb, BT, C, C);
        ln_kernel<0><<<BT, 256>>>(t1, cln_g + i0 * C, cln_b + i0 * C, nullb, nullb);
        // ---- conv block 2: dwconv -> pw GEMM -> LN(hilo out) ----
        long i1 = (long)(l * NC + 1);
        dwconv_kernel<<<BT, C>>>(t1, dw_w + i1 * C * K, dw_b + i1 * C, a5h, a5l);
        tgemm_kernel<0,0><<<gCC, 256, SMEM>>>(a5h, a5l, whi + OFF_PW + i1 * C * C,
            wlo + OFF_PW + i1 * C * C, pw_b + i1 * C, t1, nullb, nullb, BT, C, C);
        ln_kernel<2><<<BT, 256>>>(t1, cln_g + i1 * C, cln_b + i1 * C, a5h, a5l);
        // ---- attention: QKV (hilo out) -> mma attention -> WO -> LN(hilo) ----
        long lw = (long)l * C * C;
        tgemm_kernel<0,1><<<gCC, 256, SMEM>>>(a5h, a5l, whi + OFF_WQ + lw, wlo + OFF_WQ + lw,
            bq + (long)l * C, nullf, qh, ql, BT, C, C);
        tgemm_kernel<0,1><<<gCC, 256, SMEM>>>(a5h, a5l, whi + OFF_WK + lw, wlo + OFF_WK + lw,
            bk + (long)l * C, nullf, kh, kl, BT, C, C);
        tgemm_kernel<0,1><<<gCC, 256, SMEM>>>(a5h, a5l, whi + OFF_WV + lw, wlo + OFF_WV + lw,
            bv + (long)l * C, nullf, vh, vl, BT, C, C);
        attn_kernel<<<dim3(8, NH, B), 128, ASMEM>>>(qh, ql, kh, kl, vh, vl, a5h, a5l);
        tgemm_kernel<0,0><<<gCC, 256, SMEM>>>(a5h, a5l, whi + OFF_WO + lw, wlo + OFF_WO + lw,
            bo + (long)l * C, t1, nullb, nullb, BT, C, C);
        ln_kernel<2><<<BT, 256>>>(t1, aln_g + (long)l * C, aln_b + (long)l * C, a5h, a5l);
        // ---- FFN: W1+ReLU (hilo out, stride 2048) -> W2 -> LN(fp32 in d_out) ----
        tgemm_kernel<1,1><<<gCH, 256, SMEM>>>(a5h, a5l, whi + OFF_W1 + (long)l * HID * C,
            wlo + OFF_W1 + (long)l * HID * C, b1 + (long)l * HID, nullf, a2h, a2l, BT, HID, C);
        float* outl = out + (long)l * BTC;
        tgemm_kernel<0,0><<<gCC, 256, SMEM>>>(a2h, a2l, whi + OFF_W2 + (long)l * C * HID,
            wlo + OFF_W2 + (long)l * C * HID, b2 + (long)l * C, outl, nullb, nullb, BT, C, HID);
        ln_kernel<0><<<BT, 256>>>(outl, fln_g + (long)l * C, fln_b + (long)l * C, nullb, nullb);
        cur = outl;
    }
}

// round 12
// speedup vs baseline: 3.1276x; 1.0164x over previous
#include <cuda_runtime.h>
#include <cuda_bf16.h>
#include <cstdint>
#include <math.h>

using std::uint32_t;
using std::uint64_t;

namespace cfg {
constexpr int B = 16, T = 500, C = 512, K = 7, NH = 8, HD = 64, HID = 2048, L = 3, NC = 2;
constexpr int BT = B * T;                  // 8000
constexpr int MPAD = 8064;                 // 63 * 128
constexpr long BTC = (long)BT * C;
constexpr float SCALE = 0.125f;
constexpr long OFF_PW = 0;
constexpr long LEN_PW = (long)L * NC * C * C;
constexpr long OFF_WQ = OFF_PW + LEN_PW;
constexpr long LEN_W  = (long)L * C * C;
constexpr long OFF_WK = OFF_WQ + LEN_W;
constexpr long OFF_WV = OFF_WK + LEN_W;
constexpr long OFF_WO = OFF_WV + LEN_W;
constexpr long OFF_W1 = OFF_WO + LEN_W;
constexpr long LEN_W1 = (long)L * HID * C;
constexpr long OFF_W2 = OFF_W1 + LEN_W1;
constexpr long LEN_W2 = (long)L * C * HID;
constexpr long WTOT   = OFF_W2 + LEN_W2;
}

// ---------------------------------------------------------------------------
// Scratch (device globals; no allocation allowed)
// ---------------------------------------------------------------------------
__device__ float g_t1[cfg::BT * cfg::C];
__device__ __nv_bfloat16 g_a512h[(long)cfg::MPAD * cfg::C];
__device__ __nv_bfloat16 g_a512l[(long)cfg::MPAD * cfg::C];
__device__ __nv_bfloat16 g_a2kh [(long)cfg::MPAD * cfg::HID];
__device__ __nv_bfloat16 g_a2kl [(long)cfg::MPAD * cfg::HID];
__device__ __nv_bfloat16 g_qh[(long)cfg::BT * cfg::C];
__device__ __nv_bfloat16 g_ql[(long)cfg::BT * cfg::C];
__device__ __nv_bfloat16 g_kh[(long)cfg::BT * cfg::C];
__device__ __nv_bfloat16 g_kl[(long)cfg::BT * cfg::C];
__device__ __nv_bfloat16 g_vh[(long)cfg::BT * cfg::C];
__device__ __nv_bfloat16 g_vl[(long)cfg::BT * cfg::C];
__device__ __nv_bfloat16 g_whi[cfg::WTOT];
__device__ __nv_bfloat16 g_wlo[cfg::WTOT];

// ---------------------------------------------------------------------------
// PTX helpers (plain sm_80+ only; compute_103 rejects the 'a'-suffix ISA)
// ---------------------------------------------------------------------------
__device__ __forceinline__ uint32_t smem_u32(const void* p) {
    uint32_t a;
    asm("{ .reg .u64 t; cvta.to.shared.u64 t, %1; cvt.u32.u64 %0, t; }" : "=r"(a) : "l"(p));
    return a;
}
__device__ __forceinline__ void cp_async16(uint32_t dst, const void* src) {
    asm volatile("cp.async.ca.shared.global [%0], [%1], 16;" :: "r"(dst), "l"(src));
}
__device__ __forceinline__ void cp_commit() {
    asm volatile("cp.async.commit_group;" ::: "memory");
}
__device__ __forceinline__ void ldm_x4(uint32_t* a, uint32_t addr) {
    asm volatile("ldmatrix.sync.aligned.m8n8.x4.shared.b16 {%0,%1,%2,%3}, [%4];"
                 : "=r"(a[0]), "=r"(a[1]), "=r"(a[2]), "=r"(a[3]) : "r"(addr));
}
__device__ __forceinline__ void ldm_x2(uint32_t* b, uint32_t addr) {
    asm volatile("ldmatrix.sync.aligned.m8n8.x2.shared.b16 {%0,%1}, [%2];"
                 : "=r"(b[0]), "=r"(b[1]) : "r"(addr));
}
__device__ __forceinline__ void mma_bf16(float* d, const uint32_t* a, const uint32_t* b) {
    asm volatile(
        "mma.sync.aligned.m16n8k16.row.col.f32.bf16.bf16.f32 "
        "{%0,%1,%2,%3},{%4,%5,%6,%7},{%8,%9},{%0,%1,%2,%3};"
        : "+f"(d[0]), "+f"(d[1]), "+f"(d[2]), "+f"(d[3])
        : "r"(a[0]), "r"(a[1]), "r"(a[2]), "r"(a[3]), "r"(b[0]), "r"(b[1]));
}
__device__ __forceinline__ uint32_t pack_bf16(__nv_bfloat16 a, __nv_bfloat16 b) {
    __nv_bfloat162 t(a, b);            // a = low half
    return *reinterpret_cast<uint32_t*>(&t);
}
__device__ __forceinline__ void split2(float a, float b, uint32_t& hi, uint32_t& lo) {
    __nv_bfloat16 ah = __float2bfloat16(a), bh = __float2bfloat16(b);
    float ar = a - __bfloat162float(ah), br = b - __bfloat162float(bh);
    hi = pack_bf16(ah, bh);
    lo = pack_bf16(__float2bfloat16(ar), __float2bfloat16(br));
}

// ---------------------------------------------------------------------------
// fp32 -> (hi, lo) bf16 weight converter
// ---------------------------------------------------------------------------
__global__ void cvt_w_kernel(const float* __restrict__ in, __nv_bfloat16* __restrict__ hi,
                             __nv_bfloat16* __restrict__ lo, long n) {
    long i = (long)blockIdx.x * blockDim.x + threadIdx.x;
    if (i >= n) return;
    float v = in[i];
    __nv_bfloat16 h = __float2bfloat16(v);
    hi[i] = h;
    lo[i] = __float2bfloat16(v - __bfloat162float(h));
}

__global__ void zero_pad_kernel(__nv_bfloat16* a5h, __nv_bfloat16* a5l,
                                __nv_bfloat16* a2h, __nv_bfloat16* a2l) {
    int i = blockIdx.x * blockDim.x + threadIdx.x;
    if (i < 64 * 512) {
        long o = (long)8000 * 512 + i;
        a5h[o] = __nv_bfloat16(0.f); a5l[o] = __nv_bfloat16(0.f);
    }
    if (i < 64 * 2048) {
        long o = (long)8000 * 2048 + i;
        a2h[o] = __nv_bfloat16(0.f); a2l[o] = __nv_bfloat16(0.f);
    }
}

// ---------------------------------------------------------------------------
// mma.sync GEMM, NT2: C[M,N] = A[M,K] @ W[N,K]^T + bias.
// CTA computes 128 x 256 (two 128-wide N halves) so A is staged ONCE per
// chunk for 2 output tiles: 6 smem tiles/chunk (Ahi,Alo,Bhi0,Blo0,Bhi1,Blo1).
// K-chunk 64, cp.async double buffer (192 KB). 8 warps, warp tile 64x32 per
// half. Split precision: D += Ahi*Bhi + Alo*Bhi + Ahi*Blo.
// RELU optional; HILO: write split-bf16 (Ohi/Olo) instead of fp32 Cout.
// ---------------------------------------------------------------------------
template <int RELU, int HILO>
__global__ void __launch_bounds__(256, 1)
tgemm_kernel(const __nv_bfloat16* __restrict__ Ahi, const __nv_bfloat16* __restrict__ Alo,
             const __nv_bfloat16* __restrict__ Bhi, const __nv_bfloat16* __restrict__ Blo,
             const float* __restrict__ bias, float* __restrict__ Cout,
             __nv_bfloat16* __restrict__ Ohi, __nv_bfloat16* __restrict__ Olo,
             int Mout, int N, int Kd) {
    extern __shared__ char smc[];
    const uint32_t sbase = smem_u32(smc);
    constexpr int TILE = 16384;
    const int tid  = threadIdx.x;
    const int warp = tid >> 5, lane = tid & 31;
    const int n0 = blockIdx.x * 256, m0 = blockIdx.y * 128;
    const int wm = (warp >> 2) * 64;
    const int wn = (warp & 3) * 32;

    float acc[2][4][4][4];   // [half][mt][nt][frag]
#pragma unroll
    for (int h = 0; h < 2; h++)
#pragma unroll
        for (int i = 0; i < 4; i++)
#pragma unroll
            for (int j = 0; j < 4; j++)
#pragma unroll
                for (int q = 0; q < 4; q++) acc[h][i][j][q] = 0.f;

    const __nv_bfloat16* srcs[6] = {
        Ahi + (long)m0 * Kd,         Alo + (long)m0 * Kd,
        Bhi + (long)n0 * Kd,         Blo + (long)n0 * Kd,
        Bhi + (long)(n0 + 128) * Kd, Blo + (long)(n0 + 128) * Kd };
    const int nch = Kd >> 6;

    auto stage = [&](int c, int b) {
        const int k0 = c << 6;
        const uint32_t bufb = sbase + b * 6 * TILE;
#pragma unroll
        for (int tI = 0; tI < 6; tI++) {
            const __nv_bfloat16* src = srcs[tI] + k0;
            const uint32_t dstb = bufb + tI * TILE;
#pragma unroll
            for (int i = 0; i < 4; i++) {
                int idx = tid * 4 + i;
                int r = idx >> 3, ch = idx & 7;
                uint32_t dst = dstb + r * 128 + ((ch ^ (r & 7)) << 4);
                cp_async16(dst, src + (long)r * Kd + ch * 8);
            }
        }
        cp_commit();
    };

    stage(0, 0);
    for (int c = 0; c < nch; c++) {
        const int b = c & 1;
        if (c + 1 < nch) {
            stage(c + 1, b ^ 1);
            asm volatile("cp.async.wait_group 1;" ::: "memory");
        } else {
            asm volatile("cp.async.wait_group 0;" ::: "memory");
        }
        __syncthreads();

        const uint32_t tAhi = sbase + b * 6 * TILE;
        const uint32_t tAlo = tAhi + TILE;

#pragma unroll
        for (int kk = 0; kk < 64; kk += 16) {
            uint32_t ahi[4][4], alo[4][4];
            {
                const int ar = (lane & 15);
                const int ac = (kk >> 3) + (lane >> 4);
#pragma unroll
                for (int mt = 0; mt < 4; mt++) {
                    int r = wm + mt * 16 + ar;
                    uint32_t off = r * 128 + ((ac ^ (r & 7)) << 4);
                    ldm_x4(ahi[mt], tAhi + off);
                    ldm_x4(alo[mt], tAlo + off);
                }
            }
#pragma unroll
            for (int h = 0; h < 2; h++) {
                const uint32_t tBhi = tAhi + (2 + 2 * h) * TILE;
                const uint32_t tBlo = tAhi + (3 + 2 * h) * TILE;
                uint32_t bhi[4][2], blo[4][2];
                {
                    const int br = (lane & 7);
                    const int bc = (kk >> 3) + ((lane >> 3) & 1);
#pragma unroll
                    for (int nt = 0; nt < 4; nt++) {
                        int r = wn + nt * 8 + br;
                        uint32_t off = r * 128 + ((bc ^ (r & 7)) << 4);
                        ldm_x2(bhi[nt], tBhi + off);
                        ldm_x2(blo[nt], tBlo + off);
                    }
                }
#pragma unroll
                for (int mt = 0; mt < 4; mt++)
#pragma unroll
                    for (int nt = 0; nt < 4; nt++) {
                        mma_bf16(acc[h][mt][nt], ahi[mt], bhi[nt]);
                        mma_bf16(acc[h][mt][nt], alo[mt], bhi[nt]);
                        mma_bf16(acc[h][mt][nt], ahi[mt], blo[nt]);
                    }
            }
        }
        __syncthreads();
    }

    const int tq = lane >> 2, tr = lane & 3;
#pragma unroll
    for (int h = 0; h < 2; h++) {
#pragma unroll
        for (int mt = 0; mt < 4; mt++) {
            const int row0 = m0 + wm + mt * 16;
#pragma unroll
            for (int nt = 0; nt < 4; nt++) {
                const int col = n0 + h * 128 + wn + nt * 8 + tr * 2;
                const float2 bv = *(const float2*)(bias + col);
                float* a4 = acc[h][mt][nt];
                int r1 = row0 + tq, r2 = row0 + tq + 8;
                float o1x = a4[0] + bv.x, o1y = a4[1] + bv.y;
                float o2x = a4[2] + bv.x, o2y = a4[3] + bv.y;
                if (RELU) {
                    o1x = fmaxf(o1x, 0.f); o1y = fmaxf(o1y, 0.f);
                    o2x = fmaxf(o2x, 0.f); o2y = fmaxf(o2y, 0.f);
                }
                if (r1 < Mout) {
                    if (HILO) {
                        uint32_t hh, ll;
                        split2(o1x, o1y, hh, ll);
                        *(uint32_t*)(Ohi + (long)r1 * N + col) = hh;
                        *(uint32_t*)(Olo + (long)r1 * N + col) = ll;
                    } else {
                        float2 o = {o1x, o1y};
                        *(float2*)(Cout + (long)r1 * N + col) = o;
                    }
                }
                if (r2 < Mout) {
                    if (HILO) {
                        uint32_t hh, ll;
                        split2(o2x, o2y, hh, ll);
                        *(uint32_t*)(Ohi + (long)r2 * N + col) = hh;
                        *(uint32_t*)(Olo + (long)r2 * N + col) = ll;
                    } else {
                        float2 o = {o2x, o2y};
                        *(float2*)(Cout + (long)r2 * N + col) = o;
                    }
                }
            }
        }
    }
}

// ---------------------------------------------------------------------------
// Depthwise conv along T (K=7, pad=3) + bias; writes split-bf16 hi/lo.
// ---------------------------------------------------------------------------
__global__ void dwconv_kernel(const float* __restrict__ x, const float* __restrict__ w,
                              const float* __restrict__ bias,
                              __nv_bfloat16* __restrict__ oh, __nv_bfloat16* __restrict__ ol) {
    int bt = blockIdx.x;
    int t  = bt % cfg::T;
    int c  = threadIdx.x;
    const float* xr = x + (long)(bt - t) * cfg::C + c;
    float wr[7];
#pragma unroll
    for (int k = 0; k < 7; k++) wr[k] = w[c * 7 + k];
    float acc = bias[c];
#pragma unroll
    for (int k = 0; k < 7; k++) {
        int tt = t + k - 3;
        if (tt >= 0 && tt < cfg::T) acc += xr[(long)tt * cfg::C] * wr[k];
    }
    __nv_bfloat16 h = __float2bfloat16(acc);
    oh[(long)bt * cfg::C + c] = h;
    ol[(long)bt * cfg::C + c] = __float2bfloat16(acc - __bfloat162float(h));
}

// ---------------------------------------------------------------------------
// LayerNorm over C=512. MODE 0: fp32 in place. MODE 2: split-bf16 out only.
// ---------------------------------------------------------------------------
template <int MODE>
__global__ void ln_kernel(float* __restrict__ x, const float* __restrict__ g,
                          const float* __restrict__ b,
                          __nv_bfloat16* __restrict__ oh, __nv_bfloat16* __restrict__ ol) {
    long row = blockIdx.x;
    float* xr = x + row * cfg::C;
    int tid = threadIdx.x;
    float v0 = xr[tid], v1 = xr[tid + 256];
    float s = v0 + v1, ss = v0 * v0 + v1 * v1;
#pragma unroll
    for (int o = 16; o > 0; o >>= 1) {
        s  += __shfl_xor_sync(~0u, s, o);
        ss += __shfl_xor_sync(~0u, ss, o);
    }
    __shared__ float sh_s[8], sh_ss[8];
    int w = tid >> 5, ln = tid & 31;
    if (ln == 0) { sh_s[w] = s; sh_ss[w] = ss; }
    __syncthreads();
    float ts = 0.f, tss = 0.f;
#pragma unroll
    for (int i = 0; i < 8; i++) { ts += sh_s[i]; tss += sh_ss[i]; }
    float mean = ts * (1.f / 512.f);
    float var  = tss * (1.f / 512.f) - mean * mean;
    float rinv = rsqrtf(var + 1e-5f);
    float o0 = (v0 - mean) * rinv * g[tid]       + b[tid];
    float o1 = (v1 - mean) * rinv * g[tid + 256] + b[tid + 256];
    if (MODE == 0) {
        xr[tid] = o0; xr[tid + 256] = o1;
    } else {
        __nv_bfloat16 h0 = __float2bfloat16(o0), h1 = __float2bfloat16(o1);
        oh[row * cfg::C + tid]       = h0;
        oh[row * cfg::C + tid + 256] = h1;
        ol[row * cfg::C + tid]       = __float2bfloat16(o0 - __bfloat162float(h0));
        ol[row * cfg::C + tid + 256] = __float2bfloat16(o1 - __bfloat162float(h1));
    }
}

// ---------------------------------------------------------------------------
// Tensor-core causal flash attention, 3-pass split-bf16 for QK^T and PV.
// ---------------------------------------------------------------------------
__global__ void __launch_bounds__(128)
attn_kernel(const __nv_bfloat16* __restrict__ qh, const __nv_bfloat16* __restrict__ ql,
            const __nv_bfloat16* __restrict__ kh, const __nv_bfloat16* __restrict__ kl,
            const __nv_bfloat16* __restrict__ vh, const __nv_bfloat16* __restrict__ vl,
            __nv_bfloat16* __restrict__ oh, __nv_bfloat16* __restrict__ ol) {
    extern __shared__ char smc[];
    const uint32_t sbase = smem_u32(smc);
    constexpr int TB = 64 * 72 * 2;   // 9216 bytes per tile
    const uint32_t QH = 0, QL = TB, KH = 2 * TB, KL = 3 * TB, VH = 4 * TB, VL = 5 * TB;
    __nv_bfloat16* sp = (__nv_bfloat16*)smc;

    const int qt = blockIdx.x, hh = blockIdx.y, bb = blockIdx.z;
    const int tid = threadIdx.x;
    const int warp = tid >> 5, lane = tid & 31;
    const long brow = (long)bb * cfg::T;
    const int hc = hh * cfg::HD;

#pragma unroll
    for (int i = 0; i < 16; i++) {
        int idx = tid + i * 128;
        int rr = idx >> 5, d2 = idx & 31;
        int iq = qt * 64 + rr;
        uint32_t a = 0, c = 0;
        if (iq < cfg::T) {
            a = *(const uint32_t*)(qh + (brow + iq) * cfg::C + hc + d2 * 2);
            c = *(const uint32_t*)(ql + (brow + iq) * cfg::C + hc + d2 * 2);
        }
        *(uint32_t*)(smc + QH + rr * 144 + d2 * 4) = a;
        *(uint32_t*)(smc + QL + rr * 144 + d2 * 4) = c;
    }

    float m0 = -1e30f, m1 = -1e30f, l0 = 0.f, l1 = 0.f;
    float O[8][4];
#pragma unroll
    for (int i = 0; i < 8; i++)
#pragma unroll
        for (int j = 0; j < 4; j++) O[i][j] = 0.f;

    const int wm = warp * 16;
    const int rowg0 = qt * 64 + wm + (lane >> 2);
    const int rowg1 = rowg0 + 8;

    for (int ch = 0; ch <= qt; ch++) {
        const int kv0 = ch * 64;
        __syncthreads();
#pragma unroll
        for (int i = 0; i < 16; i++) {
            int idx = tid + i * 128;
            int rr = idx >> 5, d2 = idx & 31;
            int jg = kv0 + rr;
            uint32_t ka = 0, kc = 0, va = 0, vc = 0;
            if (jg < cfg::T) {
                ka = *(const uint32_t*)(kh + (brow + jg) * cfg::C + hc + d2 * 2);
                kc = *(const uint32_t*)(kl + (brow + jg) * cfg::C + hc + d2 * 2);
                va = *(const uint32_t*)(vh + (brow + jg) * cfg::C + hc + d2 * 2);
                vc = *(const uint32_t*)(vl + (brow + jg) * cfg::C + hc + d2 * 2);
            }
            *(uint32_t*)(smc + KH + rr * 144 + d2 * 4) = ka;
            *(uint32_t*)(smc + KL + rr * 144 + d2 * 4) = kc;
            __nv_bfloat162 tv = *reinterpret_cast<__nv_bfloat162*>(&va);
            __nv_bfloat162 tl = *reinterpret_cast<__nv_bfloat162*>(&vc);
            sp[(VH >> 1) + (2 * d2) * 72 + rr]     = tv.x;
            sp[(VH >> 1) + (2 * d2 + 1) * 72 + rr] = tv.y;
            sp[(VL >> 1) + (2 * d2) * 72 + rr]     = tl.x;
            sp[(VL >> 1) + (2 * d2 + 1) * 72 + rr] = tl.y;
        }
        __syncthreads();

        float S[8][4];
#pragma unroll
        for (int i = 0; i < 8; i++)
#pragma unroll
            for (int j = 0; j < 4; j++) S[i][j] = 0.f;
#pragma unroll
        for (int kk = 0; kk < 64; kk += 16) {
            uint32_t qa_h[4], qa_l[4];
            {
                int r = wm + (lane & 15);
                uint32_t off = r * 144 + ((kk >> 3) + (lane >> 4)) * 16;
                ldm_x4(qa_h, sbase + QH + off);
                ldm_x4(qa_l, sbase + QL + off);
            }
#pragma unroll
            for (int nt = 0; nt < 8; nt++) {
                uint32_t kb_h[2], kb_l[2];
                int r = nt * 8 + (lane & 7);
                uint32_t off = r * 144 + ((kk >> 3) + ((lane >> 3) & 1)) * 16;
                ldm_x2(kb_h, sbase + KH + off);
                ldm_x2(kb_l, sbase + KL + off);
                mma_bf16(S[nt], qa_h, kb_h);
                mma_bf16(S[nt], qa_l, kb_h);
                mma_bf16(S[nt], qa_h, kb_l);
            }
        }
        const int colb = kv0 + (lane & 3) * 2;
#pragma unroll
        for (int nt = 0; nt < 8; nt++) {
            int c0 = colb + nt * 8, c1 = c0 + 1;
            S[nt][0] = (c0 <= rowg0 && c0 < cfg::T) ? S[nt][0] * cfg::SCALE : -1e30f;
            S[nt][1] = (c1 <= rowg0 && c1 < cfg::T) ? S[nt][1] * cfg::SCALE : -1e30f;
            S[nt][2] = (c0 <= rowg1 && c0 < cfg::T) ? S[nt][2] * cfg::SCALE : -1e30f;
            S[nt][3] = (c1 <= rowg1 && c1 < cfg::T) ? S[nt][3] * cfg::SCALE : -1e30f;
        }
        float mx0 = -1e30f, mx1 = -1e30f;
#pragma unroll
        for (int nt = 0; nt < 8; nt++) {
            mx0 = fmaxf(mx0, fmaxf(S[nt][0], S[nt][1]));
            mx1 = fmaxf(mx1, fmaxf(S[nt][2], S[nt][3]));
        }
        mx0 = fmaxf(mx0, __shfl_xor_sync(~0u, mx0, 1));
        mx0 = fmaxf(mx0, __shfl_xor_sync(~0u, mx0, 2));
        mx1 = fmaxf(mx1, __shfl_xor_sync(~0u, mx1, 1));
        mx1 = fmaxf(mx1, __shfl_xor_sync(~0u, mx1, 2));
        float mn0 = fmaxf(m0, mx0), mn1 = fmaxf(m1, mx1);
        float cr0 = __expf(m0 - mn0), cr1 = __expf(m1 - mn1);
        float ps0 = 0.f, ps1 = 0.f;
#pragma unroll
        for (int nt = 0; nt < 8; nt++) {
            S[nt][0] = __expf(S[nt][0] - mn0); ps0 += S[nt][0];
            S[nt][1] = __expf(S[nt][1] - mn0); ps0 += S[nt][1];
            S[nt][2] = __expf(S[nt][2] - mn1); ps1 += S[nt][2];
            S[nt][3] = __expf(S[nt][3] - mn1); ps1 += S[nt][3];
        }
        ps0 += __shfl_xor_sync(~0u, ps0, 1); ps0 += __shfl_xor_sync(~0u, ps0, 2);
        ps1 += __shfl_xor_sync(~0u, ps1, 1); ps1 += __shfl_xor_sync(~0u, ps1, 2);
        l0 = l0 * cr0 + ps0; l1 = l1 * cr1 + ps1;
        m0 = mn0; m1 = mn1;
#pragma unroll
        for (int nt = 0; nt < 8; nt++) {
            O[nt][0] *= cr0; O[nt][1] *= cr0;
            O[nt][2] *= cr1; O[nt][3] *= cr1;
        }
#pragma unroll
        for (int ks = 0; ks < 4; ks++) {
            uint32_t pa_h[4], pa_l[4];
            split2(S[2 * ks][0],     S[2 * ks][1],     pa_h[0], pa_l[0]);
            split2(S[2 * ks][2],     S[2 * ks][3],     pa_h[1], pa_l[1]);
            split2(S[2 * ks + 1][0], S[2 * ks + 1][1], pa_h[2], pa_l[2]);
            split2(S[2 * ks + 1][2], S[2 * ks + 1][3], pa_h[3], pa_l[3]);
#pragma unroll
            for (int nt2 = 0; nt2 < 8; nt2++) {
                uint32_t vb_h[2], vb_l[2];
                int r = nt2 * 8 + (lane & 7);
                uint32_t off = r * 144 + (ks * 2 + ((lane >> 3) & 1)) * 16;
                ldm_x2(vb_h, sbase + VH + off);
                ldm_x2(vb_l, sbase + VL + off);
                mma_bf16(O[nt2], pa_h, vb_h);
                mma_bf16(O[nt2], pa_l, vb_h);
                mma_bf16(O[nt2], pa_h, vb_l);
            }
        }
    }

    float rl0 = 1.f / l0, rl1 = 1.f / l1;
    const int iq0 = rowg0, iq1 = rowg1;
#pragma unroll
    for (int nt2 = 0; nt2 < 8; nt2++) {
        int col = hc + nt2 * 8 + (lane & 3) * 2;
        if (iq0 < cfg::T) {
            uint32_t h, l;
            split2(O[nt2][0] * rl0, O[nt2][1] * rl0, h, l);
            *(uint32_t*)(oh + (brow + iq0) * cfg::C + col) = h;
            *(uint32_t*)(ol + (brow + iq0) * cfg::C + col) = l;
        }
        if (iq1 < cfg::T) {
            uint32_t h, l;
            split2(O[nt2][2] * rl1, O[nt2][3] * rl1, h, l);
            *(uint32_t*)(oh + (brow + iq1) * cfg::C + col) = h;
            *(uint32_t*)(ol + (brow + iq1) * cfg::C + col) = l;
        }
    }
}

// ---------------------------------------------------------------------------
// Orchestration (graph-capturable)
// ---------------------------------------------------------------------------
extern "C" void kernel_launch(void* const* d_in, const int* in_sizes, int n_in,
                              void* d_out, int out_size) {
    using namespace cfg;
    const float* x     = (const float*)d_in[0];
    const float* dw_w  = (const float*)d_in[1];
    const float* dw_b  = (const float*)d_in[2];
    const float* pw_w  = (const float*)d_in[3];
    const float* pw_b  = (const float*)d_in[4];
    const float* cln_g = (const float*)d_in[5];
    const float* cln_b = (const float*)d_in[6];
    const float* wq = (const float*)d_in[7];  const float* bq = (const float*)d_in[8];
    const float* wk = (const float*)d_in[9];  const float* bk = (const float*)d_in[10];
    const float* wv = (const float*)d_in[11]; const float* bv = (const float*)d_in[12];
    const float* wo = (const float*)d_in[13]; const float* bo = (const float*)d_in[14];
    const float* aln_g = (const float*)d_in[15]; const float* aln_b = (const float*)d_in[16];
    const float* w1 = (const float*)d_in[17]; const float* b1 = (const float*)d_in[18];
    const float* w2 = (const float*)d_in[19]; const float* b2 = (const float*)d_in[20];
    const float* fln_g = (const float*)d_in[21]; const float* fln_b = (const float*)d_in[22];
    float* out = (float*)d_out;

    float* t1;
    __nv_bfloat16 *a5h, *a5l, *a2h, *a2l, *qh, *ql, *kh, *kl, *vh, *vl, *whi, *wlo;
    cudaGetSymbolAddress((void**)&t1,  g_t1);
    cudaGetSymbolAddress((void**)&a5h, g_a512h);
    cudaGetSymbolAddress((void**)&a5l, g_a512l);
    cudaGetSymbolAddress((void**)&a2h, g_a2kh);
    cudaGetSymbolAddress((void**)&a2l, g_a2kl);
    cudaGetSymbolAddress((void**)&qh,  g_qh);
    cudaGetSymbolAddress((void**)&ql,  g_ql);
    cudaGetSymbolAddress((void**)&kh,  g_kh);
    cudaGetSymbolAddress((void**)&kl,  g_kl);
    cudaGetSymbolAddress((void**)&vh,  g_vh);
    cudaGetSymbolAddress((void**)&vl,  g_vl);
    cudaGetSymbolAddress((void**)&whi, g_whi);
    cudaGetSymbolAddress((void**)&wlo, g_wlo);

    constexpr int SMEM  = 2 * 6 * 16384;    // tgemm NT2: 196,608 B
    constexpr int ASMEM = 6 * 64 * 72 * 2;  // attn:   55,296 B
    cudaFuncSetAttribute(tgemm_kernel<0,0>, cudaFuncAttributeMaxDynamicSharedMemorySize, SMEM);
    cudaFuncSetAttribute(tgemm_kernel<0,1>, cudaFuncAttributeMaxDynamicSharedMemorySize, SMEM);
    cudaFuncSetAttribute(tgemm_kernel<1,1>, cudaFuncAttributeMaxDynamicSharedMemorySize, SMEM);
    cudaFuncSetAttribute(attn_kernel,       cudaFuncAttributeMaxDynamicSharedMemorySize, ASMEM);

    auto cvtw = [&](const float* src, long off, long len) {
        cvt_w_kernel<<<(int)((len + 255) / 256), 256>>>(src, whi + off, wlo + off, len);
    };
    cvtw(pw_w, OFF_PW, LEN_PW);
    cvtw(wq,   OFF_WQ, LEN_W);
    cvtw(wk,   OFF_WK, LEN_W);
    cvtw(wv,   OFF_WV, LEN_W);
    cvtw(wo,   OFF_WO, LEN_W);
    cvtw(w1,   OFF_W1, LEN_W1);
    cvtw(w2,   OFF_W2, LEN_W2);
    zero_pad_kernel<<<(64 * 2048 + 255) / 256, 256>>>(a5h, a5l, a2h, a2l);

    dim3 gCC(C / 256, MPAD / 128);      // (2, 63)
    dim3 gCH(HID / 256, MPAD / 128);    // (8, 63)
    float* nullf = nullptr;
    __nv_bfloat16* nullb = nullptr;

    const float* cur = x;
    for (int l = 0; l < L; l++) {
        // ---- conv block 1 ----
        long i0 = (long)(l * NC + 0);
        dwconv_kernel<<<BT, C>>>(cur, dw_w + i0 * C * K, dw_b + i0 * C, a5h, a5l);
        tgemm_kernel<0,0><<<gCC, 256, SMEM>>>(a5h, a5l, whi + OFF_PW + i0 * C * C,
            wlo + OFF_PW + i0 * C * C, pw_b + i0 * C, t1, nullb, nullb, BT, C, C);
        ln_kernel<0><<<BT, 256>>>(t1, cln_g + i0 * C, cln_b + i0 * C, nullb, nullb);
        // ---- conv block 2 ----
        long i1 = (long)(l * NC + 1);
        dwconv_kernel<<<BT, C>>>(t1, dw_w + i1 * C * K, dw_b + i1 * C, a5h, a5l);
        tgemm_kernel<0,0><<<gCC, 256, SMEM>>>(a5h, a5l, whi + OFF_PW + i1 * C * C,
            wlo + OFF_PW + i1 * C * C, pw_b + i1 * C, t1, nullb, nullb, BT, C, C);
        ln_kernel<2><<<BT, 256>>>(t1, cln_g + i1 * C, cln_b + i1 * C, a5h, a5l);
        // ---- attention ----
        long lw = (long)l * C * C;
        tgemm_kernel<0,1><<<gCC, 256, SMEM>>>(a5h, a5l, whi + OFF_WQ + lw, wlo + OFF_WQ + lw,
            bq + (long)l * C, nullf, qh, ql, BT, C, C);
        tgemm_kernel<0,1><<<gCC, 256, SMEM>>>(a5h, a5l, whi + OFF_WK + lw, wlo + OFF_WK + lw,
            bk + (long)l * C, nullf, kh, kl, BT, C, C);
        tgemm_kernel<0,1><<<gCC, 256, SMEM>>>(a5h, a5l, whi + OFF_WV + lw, wlo + OFF_WV + lw,
            bv + (long)l * C, nullf, vh, vl, BT, C, C);
        attn_kernel<<<dim3(8, NH, B), 128, ASMEM>>>(qh, ql, kh, kl, vh, vl, a5h, a5l);
        tgemm_kernel<0,0><<<gCC, 256, SMEM>>>(a5h, a5l, whi + OFF_WO + lw, wlo + OFF_WO + lw,
            bo + (long)l * C, t1, nullb, nullb, BT, C, C);
        ln_kernel<2><<<BT, 256>>>(t1, aln_g + (long)l * C, aln_b + (long)l * C, a5h, a5l);
        // ---- FFN ----
        tgemm_kernel<1,1><<<gCH, 256, SMEM>>>(a5h, a5l, whi + OFF_W1 + (long)l * HID * C,
            wlo + OFF_W1 + (long)l * HID * C, b1 + (long)l * HID, nullf, a2h, a2l, BT, HID, C);
        float* outl = out + (long)l * BTC;
        tgemm_kernel<0,0><<<gCC, 256, SMEM>>>(a2h, a2l, whi + OFF_W2 + (long)l * C * HID,
            wlo + OFF_W2 + (long)l * C * HID, b2 + (long)l * C, outl, nullb, nullb, BT, C, HID);
        ln_kernel<0><<<BT, 256>>>(outl, fln_g + (long)l * C, fln_b + (long)l * C, nullb, nullb);
        cur = outl;
    }
}

// round 14
// speedup vs baseline: 3.2614x; 1.0428x over previous
#include <cuda_runtime.h>
#include <cuda_bf16.h>
#include <cstdint>
#include <math.h>

using std::uint32_t;
using std::uint64_t;

namespace cfg {
constexpr int B = 16, T = 500, C = 512, K = 7, NH = 8, HD = 64, HID = 2048, L = 3, NC = 2;
constexpr int BT = B * T;                  // 8000
constexpr int MPAD = 8064;                 // 63 * 128
constexpr long BTC = (long)BT * C;
constexpr float SCALE = 0.125f;
constexpr long OFF_PW = 0;
constexpr long LEN_PW = (long)L * NC * C * C;
constexpr long OFF_WQ = OFF_PW + LEN_PW;
constexpr long LEN_W  = (long)L * C * C;
constexpr long OFF_WK = OFF_WQ + LEN_W;
constexpr long OFF_WV = OFF_WK + LEN_W;
constexpr long OFF_WO = OFF_WV + LEN_W;
constexpr long OFF_W1 = OFF_WO + LEN_W;
constexpr long LEN_W1 = (long)L * HID * C;
constexpr long OFF_W2 = OFF_W1 + LEN_W1;
constexpr long LEN_W2 = (long)L * C * HID;
constexpr long WTOT   = OFF_W2 + LEN_W2;
}

// ---------------------------------------------------------------------------
// Scratch (device globals; no allocation allowed)
// ---------------------------------------------------------------------------
__device__ float g_t1[cfg::BT * cfg::C];
__device__ __nv_bfloat16 g_a512h[(long)cfg::MPAD * cfg::C];
__device__ __nv_bfloat16 g_a512l[(long)cfg::MPAD * cfg::C];
__device__ __nv_bfloat16 g_a2kh [(long)cfg::MPAD * cfg::HID];
__device__ __nv_bfloat16 g_a2kl [(long)cfg::MPAD * cfg::HID];
__device__ __nv_bfloat16 g_qh[(long)cfg::BT * cfg::C];
__device__ __nv_bfloat16 g_ql[(long)cfg::BT * cfg::C];
__device__ __nv_bfloat16 g_kh[(long)cfg::BT * cfg::C];
__device__ __nv_bfloat16 g_kl[(long)cfg::BT * cfg::C];
__device__ __nv_bfloat16 g_vh[(long)cfg::BT * cfg::C];
__device__ __nv_bfloat16 g_vl[(long)cfg::BT * cfg::C];
__device__ __nv_bfloat16 g_whi[cfg::WTOT];
__device__ __nv_bfloat16 g_wlo[cfg::WTOT];

// ---------------------------------------------------------------------------
// PTX helpers (plain sm_80+ only; compute_103 rejects the 'a'-suffix ISA)
// ---------------------------------------------------------------------------
__device__ __forceinline__ uint32_t smem_u32(const void* p) {
    uint32_t a;
    asm("{ .reg .u64 t; cvta.to.shared.u64 t, %1; cvt.u32.u64 %0, t; }" : "=r"(a) : "l"(p));
    return a;
}
__device__ __forceinline__ void cp_async16(uint32_t dst, const void* src) {
    asm volatile("cp.async.ca.shared.global [%0], [%1], 16;" :: "r"(dst), "l"(src));
}
__device__ __forceinline__ void cp_commit() {
    asm volatile("cp.async.commit_group;" ::: "memory");
}
__device__ __forceinline__ void ldm_x4(uint32_t* a, uint32_t addr) {
    asm volatile("ldmatrix.sync.aligned.m8n8.x4.shared.b16 {%0,%1,%2,%3}, [%4];"
                 : "=r"(a[0]), "=r"(a[1]), "=r"(a[2]), "=r"(a[3]) : "r"(addr));
}
__device__ __forceinline__ void ldm_x2(uint32_t* b, uint32_t addr) {
    asm volatile("ldmatrix.sync.aligned.m8n8.x2.shared.b16 {%0,%1}, [%2];"
                 : "=r"(b[0]), "=r"(b[1]) : "r"(addr));
}
__device__ __forceinline__ void mma_bf16(float* d, const uint32_t* a, const uint32_t* b) {
    asm volatile(
        "mma.sync.aligned.m16n8k16.row.col.f32.bf16.bf16.f32 "
        "{%0,%1,%2,%3},{%4,%5,%6,%7},{%8,%9},{%0,%1,%2,%3};"
        : "+f"(d[0]), "+f"(d[1]), "+f"(d[2]), "+f"(d[3])
        : "r"(a[0]), "r"(a[1]), "r"(a[2]), "r"(a[3]), "r"(b[0]), "r"(b[1]));
}
__device__ __forceinline__ uint32_t pack_bf16(__nv_bfloat16 a, __nv_bfloat16 b) {
    __nv_bfloat162 t(a, b);            // a = low half
    return *reinterpret_cast<uint32_t*>(&t);
}
__device__ __forceinline__ void split2(float a, float b, uint32_t& hi, uint32_t& lo) {
    __nv_bfloat16 ah = __float2bfloat16(a), bh = __float2bfloat16(b);
    float ar = a - __bfloat162float(ah), br = b - __bfloat162float(bh);
    hi = pack_bf16(ah, bh);
    lo = pack_bf16(__float2bfloat16(ar), __float2bfloat16(br));
}

// ---------------------------------------------------------------------------
// fp32 -> (hi, lo) bf16 weight converter
// ---------------------------------------------------------------------------
__global__ void cvt_w_kernel(const float* __restrict__ in, __nv_bfloat16* __restrict__ hi,
                             __nv_bfloat16* __restrict__ lo, long n) {
    long i = (long)blockIdx.x * blockDim.x + threadIdx.x;
    if (i >= n) return;
    float v = in[i];
    __nv_bfloat16 h = __float2bfloat16(v);
    hi[i] = h;
    lo[i] = __float2bfloat16(v - __bfloat162float(h));
}

__global__ void zero_pad_kernel(__nv_bfloat16* a5h, __nv_bfloat16* a5l,
                                __nv_bfloat16* a2h, __nv_bfloat16* a2l) {
    int i = blockIdx.x * blockDim.x + threadIdx.x;
    if (i < 64 * 512) {
        long o = (long)8000 * 512 + i;
        a5h[o] = __nv_bfloat16(0.f); a5l[o] = __nv_bfloat16(0.f);
    }
    if (i < 64 * 2048) {
        long o = (long)8000 * 2048 + i;
        a2h[o] = __nv_bfloat16(0.f); a2l[o] = __nv_bfloat16(0.f);
    }
}

// ---------------------------------------------------------------------------
// mma.sync GEMM: C[M,N] = A[M,K] @ W[N,K]^T + bias.
// 128x128 CTA tile, K-chunk 64, SINGLE-buffered smem (64 KB) at 2 CTAs/SM:
// cross-CTA overlap hides each CTA's staging phase. 8 warps, warp tile 64x32.
// Inner loop B-outer/A-inner to cap live registers (~110) at the 128 limit.
// Split precision: D += Ahi*Bhi + Alo*Bhi + Ahi*Blo.
// RELU optional; HILO: write split-bf16 (Ohi/Olo) instead of fp32 Cout.
// ---------------------------------------------------------------------------
template <int RELU, int HILO>
__global__ void __launch_bounds__(256, 2)
tgemm_kernel(const __nv_bfloat16* __restrict__ Ahi, const __nv_bfloat16* __restrict__ Alo,
             const __nv_bfloat16* __restrict__ Bhi, const __nv_bfloat16* __restrict__ Blo,
             const float* __restrict__ bias, float* __restrict__ Cout,
             __nv_bfloat16* __restrict__ Ohi, __nv_bfloat16* __restrict__ Olo,
             int Mout, int N, int Kd) {
    extern __shared__ char smc[];
    const uint32_t sbase = smem_u32(smc);
    constexpr int TILE = 16384;
    const int tid  = threadIdx.x;
    const int warp = tid >> 5, lane = tid & 31;
    const int n0 = blockIdx.x * 128, m0 = blockIdx.y * 128;
    const int wm = (warp >> 2) * 64;
    const int wn = (warp & 3) * 32;

    float acc[4][4][4];
#pragma unroll
    for (int i = 0; i < 4; i++)
#pragma unroll
        for (int j = 0; j < 4; j++)
#pragma unroll
            for (int q = 0; q < 4; q++) acc[i][j][q] = 0.f;

    const __nv_bfloat16* srcs[4] = {
        Ahi + (long)m0 * Kd, Alo + (long)m0 * Kd,
        Bhi + (long)n0 * Kd, Blo + (long)n0 * Kd };
    const int nch = Kd >> 6;

    for (int c = 0; c < nch; c++) {
        __syncthreads();           // prior iteration's ldmatrix reads complete
        const int k0 = c << 6;
#pragma unroll
        for (int tI = 0; tI < 4; tI++) {
            const __nv_bfloat16* src = srcs[tI] + k0;
            const uint32_t dstb = sbase + tI * TILE;
#pragma unroll
            for (int i = 0; i < 4; i++) {
                int idx = tid * 4 + i;
                int r = idx >> 3, ch = idx & 7;
                uint32_t dst = dstb + r * 128 + ((ch ^ (r & 7)) << 4);
                cp_async16(dst, src + (long)r * Kd + ch * 8);
            }
        }
        cp_commit();
        asm volatile("cp.async.wait_group 0;" ::: "memory");
        __syncthreads();

        const uint32_t tAhi = sbase;
        const uint32_t tAlo = sbase + TILE;
        const uint32_t tBhi = sbase + 2 * TILE;
        const uint32_t tBlo = sbase + 3 * TILE;

#pragma unroll
        for (int kk = 0; kk < 64; kk += 16) {
            uint32_t bhi[4][2], blo[4][2];
            {
                const int br = (lane & 7);
                const int bc = (kk >> 3) + ((lane >> 3) & 1);
#pragma unroll
                for (int nt = 0; nt < 4; nt++) {
                    int r = wn + nt * 8 + br;
                    uint32_t off = r * 128 + ((bc ^ (r & 7)) << 4);
                    ldm_x2(bhi[nt], tBhi + off);
                    ldm_x2(blo[nt], tBlo + off);
                }
            }
            const int ar = (lane & 15);
            const int ac = (kk >> 3) + (lane >> 4);
#pragma unroll
            for (int mt = 0; mt < 4; mt++) {
                uint32_t ahi4[4], alo4[4];
                int r = wm + mt * 16 + ar;
                uint32_t off = r * 128 + ((ac ^ (r & 7)) << 4);
                ldm_x4(ahi4, tAhi + off);
                ldm_x4(alo4, tAlo + off);
#pragma unroll
                for (int nt = 0; nt < 4; nt++) {
                    mma_bf16(acc[mt][nt], ahi4, bhi[nt]);
                    mma_bf16(acc[mt][nt], alo4, bhi[nt]);
                    mma_bf16(acc[mt][nt], ahi4, blo[nt]);
                }
            }
        }
    }

    const int tq = lane >> 2, tr = lane & 3;
#pragma unroll
    for (int mt = 0; mt < 4; mt++) {
        const int row0 = m0 + wm + mt * 16;
#pragma unroll
        for (int nt = 0; nt < 4; nt++) {
            const int col = n0 + wn + nt * 8 + tr * 2;
            const float2 bv = *(const float2*)(bias + col);
            float* a4 = acc[mt][nt];
            int r1 = row0 + tq, r2 = row0 + tq + 8;
            float o1x = a4[0] + bv.x, o1y = a4[1] + bv.y;
            float o2x = a4[2] + bv.x, o2y = a4[3] + bv.y;
            if (RELU) {
                o1x = fmaxf(o1x, 0.f); o1y = fmaxf(o1y, 0.f);
                o2x = fmaxf(o2x, 0.f); o2y = fmaxf(o2y, 0.f);
            }
            if (r1 < Mout) {
                if (HILO) {
                    uint32_t hh, ll;
                    split2(o1x, o1y, hh, ll);
                    *(uint32_t*)(Ohi + (long)r1 * N + col) = hh;
                    *(uint32_t*)(Olo + (long)r1 * N + col) = ll;
                } else {
                    float2 o = {o1x, o1y};
                    *(float2*)(Cout + (long)r1 * N + col) = o;
                }
            }
            if (r2 < Mout) {
                if (HILO) {
                    uint32_t hh, ll;
                    split2(o2x, o2y, hh, ll);
                    *(uint32_t*)(Ohi + (long)r2 * N + col) = hh;
                    *(uint32_t*)(Olo + (long)r2 * N + col) = ll;
                } else {
                    float2 o = {o2x, o2y};
                    *(float2*)(Cout + (long)r2 * N + col) = o;
                }
            }
        }
    }
}

// ---------------------------------------------------------------------------
// Depthwise conv along T (K=7, pad=3) + bias; writes split-bf16 hi/lo.
// ---------------------------------------------------------------------------
__global__ void dwconv_kernel(const float* __restrict__ x, const float* __restrict__ w,
                              const float* __restrict__ bias,
                              __nv_bfloat16* __restrict__ oh, __nv_bfloat16* __restrict__ ol) {
    int bt = blockIdx.x;
    int t  = bt % cfg::T;
    int c  = threadIdx.x;
    const float* xr = x + (long)(bt - t) * cfg::C + c;
    float wr[7];
#pragma unroll
    for (int k = 0; k < 7; k++) wr[k] = w[c * 7 + k];
    float acc = bias[c];
#pragma unroll
    for (int k = 0; k < 7; k++) {
        int tt = t + k - 3;
        if (tt >= 0 && tt < cfg::T) acc += xr[(long)tt * cfg::C] * wr[k];
    }
    __nv_bfloat16 h = __float2bfloat16(acc);
    oh[(long)bt * cfg::C + c] = h;
    ol[(long)bt * cfg::C + c] = __float2bfloat16(acc - __bfloat162float(h));
}

// ---------------------------------------------------------------------------
// LayerNorm over C=512. MODE 0: fp32 in place. MODE 2: split-bf16 out only.
// ---------------------------------------------------------------------------
template <int MODE>
__global__ void ln_kernel(float* __restrict__ x, const float* __restrict__ g,
                          const float* __restrict__ b,
                          __nv_bfloat16* __restrict__ oh, __nv_bfloat16* __restrict__ ol) {
    long row = blockIdx.x;
    float* xr = x + row * cfg::C;
    int tid = threadIdx.x;
    float v0 = xr[tid], v1 = xr[tid + 256];
    float s = v0 + v1, ss = v0 * v0 + v1 * v1;
#pragma unroll
    for (int o = 16; o > 0; o >>= 1) {
        s  += __shfl_xor_sync(~0u, s, o);
        ss += __shfl_xor_sync(~0u, ss, o);
    }
    __shared__ float sh_s[8], sh_ss[8];
    int w = tid >> 5, ln = tid & 31;
    if (ln == 0) { sh_s[w] = s; sh_ss[w] = ss; }
    __syncthreads();
    float ts = 0.f, tss = 0.f;
#pragma unroll
    for (int i = 0; i < 8; i++) { ts += sh_s[i]; tss += sh_ss[i]; }
    float mean = ts * (1.f / 512.f);
    float var  = tss * (1.f / 512.f) - mean * mean;
    float rinv = rsqrtf(var + 1e-5f);
    float o0 = (v0 - mean) * rinv * g[tid]       + b[tid];
    float o1 = (v1 - mean) * rinv * g[tid + 256] + b[tid + 256];
    if (MODE == 0) {
        xr[tid] = o0; xr[tid + 256] = o1;
    } else {
        __nv_bfloat16 h0 = __float2bfloat16(o0), h1 = __float2bfloat16(o1);
        oh[row * cfg::C + tid]       = h0;
        oh[row * cfg::C + tid + 256] = h1;
        ol[row * cfg::C + tid]       = __float2bfloat16(o0 - __bfloat162float(h0));
        ol[row * cfg::C + tid + 256] = __float2bfloat16(o1 - __bfloat162float(h1));
    }
}

// ---------------------------------------------------------------------------
// Tensor-core causal flash attention, 3-pass split-bf16 for QK^T and PV.
// Grid (4 qtiles of 128 rows, NH, B), 256 threads (8 warps x m16 q-rows).
// smem: Qhi/Qlo [128][72], Khi/Klo [64][72], Vthi/Vtlo [64][72] (transposed).
// ---------------------------------------------------------------------------
__global__ void __launch_bounds__(256)
attn_kernel(const __nv_bfloat16* __restrict__ qh, const __nv_bfloat16* __restrict__ ql,
            const __nv_bfloat16* __restrict__ kh, const __nv_bfloat16* __restrict__ kl,
            const __nv_bfloat16* __restrict__ vh, const __nv_bfloat16* __restrict__ vl,
            __nv_bfloat16* __restrict__ oh, __nv_bfloat16* __restrict__ ol) {
    extern __shared__ char smc[];
    const uint32_t sbase = smem_u32(smc);
    constexpr int QTB = 128 * 72 * 2;   // 18432
    constexpr int TB  = 64 * 72 * 2;    //  9216
    const uint32_t QH = 0, QL = QTB, KH = 2 * QTB, KL = 2 * QTB + TB,
                   VH = 2 * QTB + 2 * TB, VL = 2 * QTB + 3 * TB;
    __nv_bfloat16* sp = (__nv_bfloat16*)smc;

    const int qt = blockIdx.x, hh = blockIdx.y, bb = blockIdx.z;
    const int tid = threadIdx.x;
    const int warp = tid >> 5, lane = tid & 31;
    const long brow = (long)bb * cfg::T;
    const int hc = hh * cfg::HD;

    // stage Q tile: 128 rows x 32 u32 = 4096 units / 256 threads
#pragma unroll
    for (int i = 0; i < 16; i++) {
        int idx = tid + i * 256;
        int rr = idx >> 5, d2 = idx & 31;
        int iq = qt * 128 + rr;
        uint32_t a = 0, c = 0;
        if (iq < cfg::T) {
            a = *(const uint32_t*)(qh + (brow + iq) * cfg::C + hc + d2 * 2);
            c = *(const uint32_t*)(ql + (brow + iq) * cfg::C + hc + d2 * 2);
        }
        *(uint32_t*)(smc + QH + rr * 144 + d2 * 4) = a;
        *(uint32_t*)(smc + QL + rr * 144 + d2 * 4) = c;
    }

    float m0 = -1e30f, m1 = -1e30f, l0 = 0.f, l1 = 0.f;
    float O[8][4];
#pragma unroll
    for (int i = 0; i < 8; i++)
#pragma unroll
        for (int j = 0; j < 4; j++) O[i][j] = 0.f;

    const int wm = warp * 16;
    const int rowg0 = qt * 128 + wm + (lane >> 2);
    const int rowg1 = rowg0 + 8;
    const int chmax = 2 * qt + 1;

    for (int ch = 0; ch <= chmax; ch++) {
        const int kv0 = ch * 64;
        __syncthreads();
        // stage K/V chunk: 64 rows x 32 u32 = 2048 units / 256 threads
#pragma unroll
        for (int i = 0; i < 8; i++) {
            int idx = tid + i * 256;
            int rr = idx >> 5, d2 = idx & 31;
            int jg = kv0 + rr;
            uint32_t ka = 0, kc = 0, va = 0, vc = 0;
            if (jg < cfg::T) {
                ka = *(const uint32_t*)(kh + (brow + jg) * cfg::C + hc + d2 * 2);
                kc = *(const uint32_t*)(kl + (brow + jg) * cfg::C + hc + d2 * 2);
                va = *(const uint32_t*)(vh + (brow + jg) * cfg::C + hc + d2 * 2);
                vc = *(const uint32_t*)(vl + (brow + jg) * cfg::C + hc + d2 * 2);
            }
            *(uint32_t*)(smc + KH + rr * 144 + d2 * 4) = ka;
            *(uint32_t*)(smc + KL + rr * 144 + d2 * 4) = kc;
            __nv_bfloat162 tv = *reinterpret_cast<__nv_bfloat162*>(&va);
            __nv_bfloat162 tl = *reinterpret_cast<__nv_bfloat162*>(&vc);
            sp[(VH >> 1) + (2 * d2) * 72 + rr]     = tv.x;
            sp[(VH >> 1) + (2 * d2 + 1) * 72 + rr] = tv.y;
            sp[(VL >> 1) + (2 * d2) * 72 + rr]     = tl.x;
            sp[(VL >> 1) + (2 * d2 + 1) * 72 + rr] = tl.y;
        }
        __syncthreads();

        float S[8][4];
#pragma unroll
        for (int i = 0; i < 8; i++)
#pragma unroll
            for (int j = 0; j < 4; j++) S[i][j] = 0.f;
#pragma unroll
        for (int kk = 0; kk < 64; kk += 16) {
            uint32_t qa_h[4], qa_l[4];
            {
                int r = wm + (lane & 15);
                uint32_t off = r * 144 + ((kk >> 3) + (lane >> 4)) * 16;
                ldm_x4(qa_h, sbase + QH + off);
                ldm_x4(qa_l, sbase + QL + off);
            }
#pragma unroll
            for (int nt = 0; nt < 8; nt++) {
                uint32_t kb_h[2], kb_l[2];
                int r = nt * 8 + (lane & 7);
                uint32_t off = r * 144 + ((kk >> 3) + ((lane >> 3) & 1)) * 16;
                ldm_x2(kb_h, sbase + KH + off);
                ldm_x2(kb_l, sbase + KL + off);
                mma_bf16(S[nt], qa_h, kb_h);
                mma_bf16(S[nt], qa_l, kb_h);
                mma_bf16(S[nt], qa_h, kb_l);
            }
        }
        const int colb = kv0 + (lane & 3) * 2;
#pragma unroll
        for (int nt = 0; nt < 8; nt++) {
            int c0 = colb + nt * 8, c1 = c0 + 1;
            S[nt][0] = (c0 <= rowg0 && c0 < cfg::T) ? S[nt][0] * cfg::SCALE : -1e30f;
            S[nt][1] = (c1 <= rowg0 && c1 < cfg::T) ? S[nt][1] * cfg::SCALE : -1e30f;
            S[nt][2] = (c0 <= rowg1 && c0 < cfg::T) ? S[nt][2] * cfg::SCALE : -1e30f;
            S[nt][3] = (c1 <= rowg1 && c1 < cfg::T) ? S[nt][3] * cfg::SCALE : -1e30f;
        }
        float mx0 = -1e30f, mx1 = -1e30f;
#pragma unroll
        for (int nt = 0; nt < 8; nt++) {
            mx0 = fmaxf(mx0, fmaxf(S[nt][0], S[nt][1]));
            mx1 = fmaxf(mx1, fmaxf(S[nt][2], S[nt][3]));
        }
        mx0 = fmaxf(mx0, __shfl_xor_sync(~0u, mx0, 1));
        mx0 = fmaxf(mx0, __shfl_xor_sync(~0u, mx0, 2));
        mx1 = fmaxf(mx1, __shfl_xor_sync(~0u, mx1, 1));
        mx1 = fmaxf(mx1, __shfl_xor_sync(~0u, mx1, 2));
        float mn0 = fmaxf(m0, mx0), mn1 = fmaxf(m1, mx1);
        float cr0 = __expf(m0 - mn0), cr1 = __expf(m1 - mn1);
        float ps0 = 0.f, ps1 = 0.f;
#pragma unroll
        for (int nt = 0; nt < 8; nt++) {
            S[nt][0] = __expf(S[nt][0] - mn0); ps0 += S[nt][0];
            S[nt][1] = __expf(S[nt][1] - mn0); ps0 += S[nt][1];
            S[nt][2] = __expf(S[nt][2] - mn1); ps1 += S[nt][2];
            S[nt][3] = __expf(S[nt][3] - mn1); ps1 += S[nt][3];
        }
        ps0 += __shfl_xor_sync(~0u, ps0, 1); ps0 += __shfl_xor_sync(~0u, ps0, 2);
        ps1 += __shfl_xor_sync(~0u, ps1, 1); ps1 += __shfl_xor_sync(~0u, ps1, 2);
        l0 = l0 * cr0 + ps0; l1 = l1 * cr1 + ps1;
        m0 = mn0; m1 = mn1;
#pragma unroll
        for (int nt = 0; nt < 8; nt++) {
            O[nt][0] *= cr0; O[nt][1] *= cr0;
            O[nt][2] *= cr1; O[nt][3] *= cr1;
        }
#pragma unroll
        for (int ks = 0; ks < 4; ks++) {
            uint32_t pa_h[4], pa_l[4];
            split2(S[2 * ks][0],     S[2 * ks][1],     pa_h[0], pa_l[0]);
            split2(S[2 * ks][2],     S[2 * ks][3],     pa_h[1], pa_l[1]);
            split2(S[2 * ks + 1][0], S[2 * ks + 1][1], pa_h[2], pa_l[2]);
            split2(S[2 * ks + 1][2], S[2 * ks + 1][3], pa_h[3], pa_l[3]);
#pragma unroll
            for (int nt2 = 0; nt2 < 8; nt2++) {
                uint32_t vb_h[2], vb_l[2];
                int r = nt2 * 8 + (lane & 7);
                uint32_t off = r * 144 + (ks * 2 + ((lane >> 3) & 1)) * 16;
                ldm_x2(vb_h, sbase + VH + off);
                ldm_x2(vb_l, sbase + VL + off);
                mma_bf16(O[nt2], pa_h, vb_h);
                mma_bf16(O[nt2], pa_l, vb_h);
                mma_bf16(O[nt2], pa_h, vb_l);
            }
        }
    }

    float rl0 = 1.f / l0, rl1 = 1.f / l1;
    const int iq0 = rowg0, iq1 = rowg1;
#pragma unroll
    for (int nt2 = 0; nt2 < 8; nt2++) {
        int col = hc + nt2 * 8 + (lane & 3) * 2;
        if (iq0 < cfg::T) {
            uint32_t h, l;
            split2(O[nt2][0] * rl0, O[nt2][1] * rl0, h, l);
            *(uint32_t*)(oh + (brow + iq0) * cfg::C + col) = h;
            *(uint32_t*)(ol + (brow + iq0) * cfg::C + col) = l;
        }
        if (iq1 < cfg::T) {
            uint32_t h, l;
            split2(O[nt2][2] * rl1, O[nt2][3] * rl1, h, l);
            *(uint32_t*)(oh + (brow + iq1) * cfg::C + col) = h;
            *(uint32_t*)(ol + (brow + iq1) * cfg::C + col) = l;
        }
    }
}

// ---------------------------------------------------------------------------
// Orchestration (graph-capturable)
// ---------------------------------------------------------------------------
extern "C" void kernel_launch(void* const* d_in, const int* in_sizes, int n_in,
                              void* d_out, int out_size) {
    using namespace cfg;
    const float* x     = (const float*)d_in[0];
    const float* dw_w  = (const float*)d_in[1];
    const float* dw_b  = (const float*)d_in[2];
    const float* pw_w  = (const float*)d_in[3];
    const float* pw_b  = (const float*)d_in[4];
    const float* cln_g = (const float*)d_in[5];
    const float* cln_b = (const float*)d_in[6];
    const float* wq = (const float*)d_in[7];  const float* bq = (const float*)d_in[8];
    const float* wk = (const float*)d_in[9];  const float* bk = (const float*)d_in[10];
    const float* wv = (const float*)d_in[11]; const float* bv = (const float*)d_in[12];
    const float* wo = (const float*)d_in[13]; const float* bo = (const float*)d_in[14];
    const float* aln_g = (const float*)d_in[15]; const float* aln_b = (const float*)d_in[16];
    const float* w1 = (const float*)d_in[17]; const float* b1 = (const float*)d_in[18];
    const float* w2 = (const float*)d_in[19]; const float* b2 = (const float*)d_in[20];
    const float* fln_g = (const float*)d_in[21]; const float* fln_b = (const float*)d_in[22];
    float* out = (float*)d_out;

    float* t1;
    __nv_bfloat16 *a5h, *a5l, *a2h, *a2l, *qh, *ql, *kh, *kl, *vh, *vl, *whi, *wlo;
    cudaGetSymbolAddress((void**)&t1,  g_t1);
    cudaGetSymbolAddress((void**)&a5h, g_a512h);
    cudaGetSymbolAddress((void**)&a5l, g_a512l);
    cudaGetSymbolAddress((void**)&a2h, g_a2kh);
    cudaGetSymbolAddress((void**)&a2l, g_a2kl);
    cudaGetSymbolAddress((void**)&qh,  g_qh);
    cudaGetSymbolAddress((void**)&ql,  g_ql);
    cudaGetSymbolAddress((void**)&kh,  g_kh);
    cudaGetSymbolAddress((void**)&kl,  g_kl);
    cudaGetSymbolAddress((void**)&vh,  g_vh);
    cudaGetSymbolAddress((void**)&vl,  g_vl);
    cudaGetSymbolAddress((void**)&whi, g_whi);
    cudaGetSymbolAddress((void**)&wlo, g_wlo);

    constexpr int SMEM  = 4 * 16384;               // tgemm: 65,536 B (single buffer)
    constexpr int ASMEM = 2 * 128 * 72 * 2 + 4 * 64 * 72 * 2;  // attn: 73,728 B
    cudaFuncSetAttribute(tgemm_kernel<0,0>, cudaFuncAttributeMaxDynamicSharedMemorySize, SMEM);
    cudaFuncSetAttribute(tgemm_kernel<0,1>, cudaFuncAttributeMaxDynamicSharedMemorySize, SMEM);
    cudaFuncSetAttribute(tgemm_kernel<1,1>, cudaFuncAttributeMaxDynamicSharedMemorySize, SMEM);
    cudaFuncSetAttribute(attn_kernel,       cudaFuncAttributeMaxDynamicSharedMemorySize, ASMEM);

    auto cvtw = [&](const float* src, long off, long len) {
        cvt_w_kernel<<<(int)((len + 255) / 256), 256>>>(src, whi + off, wlo + off, len);
    };
    cvtw(pw_w, OFF_PW, LEN_PW);
    cvtw(wq,   OFF_WQ, LEN_W);
    cvtw(wk,   OFF_WK, LEN_W);
    cvtw(wv,   OFF_WV, LEN_W);
    cvtw(wo,   OFF_WO, LEN_W);
    cvtw(w1,   OFF_W1, LEN_W1);
    cvtw(w2,   OFF_W2, LEN_W2);
    zero_pad_kernel<<<(64 * 2048 + 255) / 256, 256>>>(a5h, a5l, a2h, a2l);

    dim3 gCC(C / 128, MPAD / 128);      // (4, 63)
    dim3 gCH(HID / 128, MPAD / 128);    // (16, 63)
    float* nullf = nullptr;
    __nv_bfloat16* nullb = nullptr;

    const float* cur = x;
    for (int l = 0; l < L; l++) {
        // ---- conv block 1 ----
        long i0 = (long)(l * NC + 0);
        dwconv_kernel<<<BT, C>>>(cur, dw_w + i0 * C * K, dw_b + i0 * C, a5h, a5l);
        tgemm_kernel<0,0><<<gCC, 256, SMEM>>>(a5h, a5l, whi + OFF_PW + i0 * C * C,
            wlo + OFF_PW + i0 * C * C, pw_b + i0 * C, t1, nullb, nullb, BT, C, C);
        ln_kernel<0><<<BT, 256>>>(t1, cln_g + i0 * C, cln_b + i0 * C, nullb, nullb);
        // ---- conv block 2 ----
        long i1 = (long)(l * NC + 1);
        dwconv_kernel<<<BT, C>>>(t1, dw_w + i1 * C * K, dw_b + i1 * C, a5h, a5l);
        tgemm_kernel<0,0><<<gCC, 256, SMEM>>>(a5h, a5l, whi + OFF_PW + i1 * C * C,
            wlo + OFF_PW + i1 * C * C, pw_b + i1 * C, t1, nullb, nullb, BT, C, C);
        ln_kernel<2><<<BT, 256>>>(t1, cln_g + i1 * C, cln_b + i1 * C, a5h, a5l);
        // ---- attention ----
        long lw = (long)l * C * C;
        tgemm_kernel<0,1><<<gCC, 256, SMEM>>>(a5h, a5l, whi + OFF_WQ + lw, wlo + OFF_WQ + lw,
            bq + (long)l * C, nullf, qh, ql, BT, C, C);
        tgemm_kernel<0,1><<<gCC, 256, SMEM>>>(a5h, a5l, whi + OFF_WK + lw, wlo + OFF_WK + lw,
            bk + (long)l * C, nullf, kh, kl, BT, C, C);
        tgemm_kernel<0,1><<<gCC, 256, SMEM>>>(a5h, a5l, whi + OFF_WV + lw, wlo + OFF_WV + lw,
            bv + (long)l * C, nullf, vh, vl, BT, C, C);
        attn_kernel<<<dim3(4, NH, B), 256, ASMEM>>>(qh, ql, kh, kl, vh, vl, a5h, a5l);
        tgemm_kernel<0,0><<<gCC, 256, SMEM>>>(a5h, a5l, whi + OFF_WO + lw, wlo + OFF_WO + lw,
            bo + (long)l * C, t1, nullb, nullb, BT, C, C);
        ln_kernel<2><<<BT, 256>>>(t1, aln_g + (long)l * C, aln_b + (long)l * C, a5h, a5l);
        // ---- FFN ----
        tgemm_kernel<1,1><<<gCH, 256, SMEM>>>(a5h, a5l, whi + OFF_W1 + (long)l * HID * C,
            wlo + OFF_W1 + (long)l * HID * C, b1 + (long)l * HID, nullf, a2h, a2l, BT, HID, C);
        float* outl = out + (long)l * BTC;
        tgemm_kernel<0,0><<<gCC, 256, SMEM>>>(a2h, a2l, whi + OFF_W2 + (long)l * C * HID,
            wlo + OFF_W2 + (long)l * C * HID, b2 + (long)l * C, outl, nullb, nullb, BT, C, HID);
        ln_kernel<0><<<BT, 256>>>(outl, fln_g + (long)l * C, fln_b + (long)l * C, nullb, nullb);
        cur = outl;
    }
}

// round 16
// speedup vs baseline: 4.0799x; 1.2510x over previous
#include <cuda_runtime.h>
#include <cuda_fp16.h>
#include <cstdint>
#include <math.h>

using std::uint32_t;
using std::uint64_t;

namespace cfg {
constexpr int B = 16, T = 500, C = 512, K = 7, NH = 8, HD = 64, HID = 2048, L = 3, NC = 2;
constexpr int BT = B * T;                  // 8000
constexpr int MPAD = 8064;                 // 63 * 128
constexpr long BTC = (long)BT * C;
constexpr float SCALE = 0.125f;
constexpr long OFF_PW = 0;
constexpr long LEN_PW = (long)L * NC * C * C;
constexpr long OFF_WQ = OFF_PW + LEN_PW;
constexpr long LEN_W  = (long)L * C * C;
constexpr long OFF_WK = OFF_WQ + LEN_W;
constexpr long OFF_WV = OFF_WK + LEN_W;
constexpr long OFF_WO = OFF_WV + LEN_W;
constexpr long OFF_W1 = OFF_WO + LEN_W;
constexpr long LEN_W1 = (long)L * HID * C;
constexpr long OFF_W2 = OFF_W1 + LEN_W1;
constexpr long LEN_W2 = (long)L * C * HID;
constexpr long WTOT   = OFF_W2 + LEN_W2;
}

// ---------------------------------------------------------------------------
// Scratch (device globals; no allocation allowed)
// ---------------------------------------------------------------------------
__device__ float g_t1[cfg::BT * cfg::C];
__device__ __half g_a512h[(long)cfg::MPAD * cfg::C];
__device__ __half g_a512l[(long)cfg::MPAD * cfg::C];
__device__ __half g_a2kh [(long)cfg::MPAD * cfg::HID];
__device__ __half g_a2kl [(long)cfg::MPAD * cfg::HID];
__device__ __half g_qh[(long)cfg::BT * cfg::C];
__device__ __half g_ql[(long)cfg::BT * cfg::C];
__device__ __half g_kh[(long)cfg::BT * cfg::C];
__device__ __half g_vh[(long)cfg::BT * cfg::C];
__device__ __half g_whi[cfg::WTOT];

// ---------------------------------------------------------------------------
// PTX helpers (plain sm_80+ only; compute_103 rejects the 'a'-suffix ISA)
// ---------------------------------------------------------------------------
__device__ __forceinline__ uint32_t smem_u32(const void* p) {
    uint32_t a;
    asm("{ .reg .u64 t; cvta.to.shared.u64 t, %1; cvt.u32.u64 %0, t; }" : "=r"(a) : "l"(p));
    return a;
}
__device__ __forceinline__ void cp_async16(uint32_t dst, const void* src) {
    asm volatile("cp.async.ca.shared.global [%0], [%1], 16;" :: "r"(dst), "l"(src));
}
__device__ __forceinline__ void cp_commit() {
    asm volatile("cp.async.commit_group;" ::: "memory");
}
__device__ __forceinline__ void ldm_x4(uint32_t* a, uint32_t addr) {
    asm volatile("ldmatrix.sync.aligned.m8n8.x4.shared.b16 {%0,%1,%2,%3}, [%4];"
                 : "=r"(a[0]), "=r"(a[1]), "=r"(a[2]), "=r"(a[3]) : "r"(addr));
}
__device__ __forceinline__ void ldm_x2(uint32_t* b, uint32_t addr) {
    asm volatile("ldmatrix.sync.aligned.m8n8.x2.shared.b16 {%0,%1}, [%2];"
                 : "=r"(b[0]), "=r"(b[1]) : "r"(addr));
}
__device__ __forceinline__ void mma_f16(float* d, const uint32_t* a, const uint32_t* b) {
    asm volatile(
        "mma.sync.aligned.m16n8k16.row.col.f32.f16.f16.f32 "
        "{%0,%1,%2,%3},{%4,%5,%6,%7},{%8,%9},{%0,%1,%2,%3};"
        : "+f"(d[0]), "+f"(d[1]), "+f"(d[2]), "+f"(d[3])
        : "r"(a[0]), "r"(a[1]), "r"(a[2]), "r"(a[3]), "r"(b[0]), "r"(b[1]));
}
__device__ __forceinline__ uint32_t pack_h2(__half a, __half b) {
    __half2 t = __halves2half2(a, b);
    return *reinterpret_cast<uint32_t*>(&t);
}
// split a pair of fp32 into packed hi/lo fp16 pairs (covers ~22 mantissa bits)
__device__ __forceinline__ void split2(float a, float b, uint32_t& hi, uint32_t& lo) {
    __half ah = __float2half(a), bh = __float2half(b);
    float ar = a - __half2float(ah), br = b - __half2float(bh);
    hi = pack_h2(ah, bh);
    lo = pack_h2(__float2half(ar), __float2half(br));
}

// ---------------------------------------------------------------------------
// fp32 -> fp16 weight converter (weights quantized to fp16; no lo term)
// ---------------------------------------------------------------------------
__global__ void cvt_w_kernel(const float* __restrict__ in, __half* __restrict__ hi, long n) {
    long i = (long)blockIdx.x * blockDim.x + threadIdx.x;
    if (i >= n) return;
    hi[i] = __float2half(in[i]);
}

__global__ void zero_pad_kernel(__half* a5h, __half* a5l, __half* a2h, __half* a2l) {
    int i = blockIdx.x * blockDim.x + threadIdx.x;
    if (i < 64 * 512) {
        long o = (long)8000 * 512 + i;
        a5h[o] = __float2half(0.f); a5l[o] = __float2half(0.f);
    }
    if (i < 64 * 2048) {
        long o = (long)8000 * 2048 + i;
        a2h[o] = __float2half(0.f); a2l[o] = __float2half(0.f);
    }
}

// ---------------------------------------------------------------------------
// mma.sync fp16 GEMM, 2-pass split: C = (Ahi + Alo) @ Bhi^T + bias.
// 128x128 CTA tile, K-chunk 64, 3 smem tiles/chunk (Ahi, Alo, Bhi),
// DOUBLE-buffered (96 KB) at 2 CTAs/SM. 8 warps, warp tile 64x32.
// OMODE: 0 = fp32 out, 1 = split fp16 hi/lo out, 2 = fp16 hi only out.
// ---------------------------------------------------------------------------
template <int RELU, int OMODE>
__global__ void __launch_bounds__(256, 2)
tgemm_kernel(const __half* __restrict__ Ahi, const __half* __restrict__ Alo,
             const __half* __restrict__ Bhi,
             const float* __restrict__ bias, float* __restrict__ Cout,
             __half* __restrict__ Ohi, __half* __restrict__ Olo,
             int Mout, int N, int Kd) {
    extern __shared__ char smc[];
    const uint32_t sbase = smem_u32(smc);
    constexpr int TILE = 16384;
    const int tid  = threadIdx.x;
    const int warp = tid >> 5, lane = tid & 31;
    const int n0 = blockIdx.x * 128, m0 = blockIdx.y * 128;
    const int wm = (warp >> 2) * 64;
    const int wn = (warp & 3) * 32;

    float acc[4][4][4];
#pragma unroll
    for (int i = 0; i < 4; i++)
#pragma unroll
        for (int j = 0; j < 4; j++)
#pragma unroll
            for (int q = 0; q < 4; q++) acc[i][j][q] = 0.f;

    const __half* srcs[3] = {
        Ahi + (long)m0 * Kd, Alo + (long)m0 * Kd, Bhi + (long)n0 * Kd };
    const int nch = Kd >> 6;

    auto stage = [&](int c, int b) {
        const int k0 = c << 6;
        const uint32_t bufb = sbase + b * 3 * TILE;
#pragma unroll
        for (int tI = 0; tI < 3; tI++) {
            const __half* src = srcs[tI] + k0;
            const uint32_t dstb = bufb + tI * TILE;
#pragma unroll
            for (int i = 0; i < 4; i++) {
                int idx = tid * 4 + i;
                int r = idx >> 3, ch = idx & 7;
                uint32_t dst = dstb + r * 128 + ((ch ^ (r & 7)) << 4);
                cp_async16(dst, src + (long)r * Kd + ch * 8);
            }
        }
        cp_commit();
    };

    stage(0, 0);
    for (int c = 0; c < nch; c++) {
        const int b = c & 1;
        if (c + 1 < nch) {
            stage(c + 1, b ^ 1);
            asm volatile("cp.async.wait_group 1;" ::: "memory");
        } else {
            asm volatile("cp.async.wait_group 0;" ::: "memory");
        }
        __syncthreads();

        const uint32_t tAhi = sbase + b * 3 * TILE;
        const uint32_t tAlo = tAhi + TILE;
        const uint32_t tBhi = tAhi + 2 * TILE;

#pragma unroll
        for (int kk = 0; kk < 64; kk += 16) {
            uint32_t bhi[4][2];
            {
                const int br = (lane & 7);
                const int bc = (kk >> 3) + ((lane >> 3) & 1);
#pragma unroll
                for (int nt = 0; nt < 4; nt++) {
                    int r = wn + nt * 8 + br;
                    uint32_t off = r * 128 + ((bc ^ (r & 7)) << 4);
                    ldm_x2(bhi[nt], tBhi + off);
                }
            }
            const int ar = (lane & 15);
            const int ac = (kk >> 3) + (lane >> 4);
#pragma unroll
            for (int mt = 0; mt < 4; mt++) {
                uint32_t ahi4[4], alo4[4];
                int r = wm + mt * 16 + ar;
                uint32_t off = r * 128 + ((ac ^ (r & 7)) << 4);
                ldm_x4(ahi4, tAhi + off);
                ldm_x4(alo4, tAlo + off);
#pragma unroll
                for (int nt = 0; nt < 4; nt++) {
                    mma_f16(acc[mt][nt], ahi4, bhi[nt]);
                    mma_f16(acc[mt][nt], alo4, bhi[nt]);
                }
            }
        }
        __syncthreads();
    }

    const int tq = lane >> 2, tr = lane & 3;
#pragma unroll
    for (int mt = 0; mt < 4; mt++) {
        const int row0 = m0 + wm + mt * 16;
#pragma unroll
        for (int nt = 0; nt < 4; nt++) {
            const int col = n0 + wn + nt * 8 + tr * 2;
            const float2 bv = *(const float2*)(bias + col);
            float* a4 = acc[mt][nt];
            int r1 = row0 + tq, r2 = row0 + tq + 8;
            float o1x = a4[0] + bv.x, o1y = a4[1] + bv.y;
            float o2x = a4[2] + bv.x, o2y = a4[3] + bv.y;
            if (RELU) {
                o1x = fmaxf(o1x, 0.f); o1y = fmaxf(o1y, 0.f);
                o2x = fmaxf(o2x, 0.f); o2y = fmaxf(o2y, 0.f);
            }
            if (r1 < Mout) {
                if (OMODE == 0) {
                    float2 o = {o1x, o1y};
                    *(float2*)(Cout + (long)r1 * N + col) = o;
                } else if (OMODE == 1) {
                    uint32_t hh, ll;
                    split2(o1x, o1y, hh, ll);
                    *(uint32_t*)(Ohi + (long)r1 * N + col) = hh;
                    *(uint32_t*)(Olo + (long)r1 * N + col) = ll;
                } else {
                    *(uint32_t*)(Ohi + (long)r1 * N + col) =
                        pack_h2(__float2half(o1x), __float2half(o1y));
                }
            }
            if (r2 < Mout) {
                if (OMODE == 0) {
                    float2 o = {o2x, o2y};
                    *(float2*)(Cout + (long)r2 * N + col) = o;
                } else if (OMODE == 1) {
                    uint32_t hh, ll;
                    split2(o2x, o2y, hh, ll);
                    *(uint32_t*)(Ohi + (long)r2 * N + col) = hh;
                    *(uint32_t*)(Olo + (long)r2 * N + col) = ll;
                } else {
                    *(uint32_t*)(Ohi + (long)r2 * N + col) =
                        pack_h2(__float2half(o2x), __float2half(o2y));
                }
            }
        }
    }
}

// ---------------------------------------------------------------------------
// Depthwise conv along T (K=7, pad=3) + bias; writes split-fp16 hi/lo.
// ---------------------------------------------------------------------------
__global__ void dwconv_kernel(const float* __restrict__ x, const float* __restrict__ w,
                              const float* __restrict__ bias,
                              __half* __restrict__ oh, __half* __restrict__ ol) {
    int bt = blockIdx.x;
    int t  = bt % cfg::T;
    int c  = threadIdx.x;
    const float* xr = x + (long)(bt - t) * cfg::C + c;
    float wr[7];
#pragma unroll
    for (int k = 0; k < 7; k++) wr[k] = w[c * 7 + k];
    float acc = bias[c];
#pragma unroll
    for (int k = 0; k < 7; k++) {
        int tt = t + k - 3;
        if (tt >= 0 && tt < cfg::T) acc += xr[(long)tt * cfg::C] * wr[k];
    }
    __half h = __float2half(acc);
    oh[(long)bt * cfg::C + c] = h;
    ol[(long)bt * cfg::C + c] = __float2half(acc - __half2float(h));
}

// ---------------------------------------------------------------------------
// LayerNorm over C=512. MODE 0: fp32 in place. MODE 2: split-fp16 out only.
// ---------------------------------------------------------------------------
template <int MODE>
__global__ void ln_kernel(float* __restrict__ x, const float* __restrict__ g,
                          const float* __restrict__ b,
                          __half* __restrict__ oh, __half* __restrict__ ol) {
    long row = blockIdx.x;
    float* xr = x + row * cfg::C;
    int tid = threadIdx.x;
    float v0 = xr[tid], v1 = xr[tid + 256];
    float s = v0 + v1, ss = v0 * v0 + v1 * v1;
#pragma unroll
    for (int o = 16; o > 0; o >>= 1) {
        s  += __shfl_xor_sync(~0u, s, o);
        ss += __shfl_xor_sync(~0u, ss, o);
    }
    __shared__ float sh_s[8], sh_ss[8];
    int w = tid >> 5, ln = tid & 31;
    if (ln == 0) { sh_s[w] = s; sh_ss[w] = ss; }
    __syncthreads();
    float ts = 0.f, tss = 0.f;
#pragma unroll
    for (int i = 0; i < 8; i++) { ts += sh_s[i]; tss += sh_ss[i]; }
    float mean = ts * (1.f / 512.f);
    float var  = tss * (1.f / 512.f) - mean * mean;
    float rinv = rsqrtf(var + 1e-5f);
    float o0 = (v0 - mean) * rinv * g[tid]       + b[tid];
    float o1 = (v1 - mean) * rinv * g[tid + 256] + b[tid + 256];
    if (MODE == 0) {
        xr[tid] = o0; xr[tid + 256] = o1;
    } else {
        __half h0 = __float2half(o0), h1 = __float2half(o1);
        oh[row * cfg::C + tid]       = h0;
        oh[row * cfg::C + tid + 256] = h1;
        ol[row * cfg::C + tid]       = __float2half(o0 - __half2float(h0));
        ol[row * cfg::C + tid + 256] = __float2half(o1 - __half2float(h1));
    }
}

// ---------------------------------------------------------------------------
// Tensor-core causal flash attention, fp16 2-pass (Q and P split; K,V fp16).
// Grid (4 qtiles of 128 rows, NH, B), 256 threads (8 warps x m16 q-rows).
// smem: Qhi/Qlo [128][72], Khi [64][72], Vthi [64][72] (transposed).
// ---------------------------------------------------------------------------
__global__ void __launch_bounds__(256)
attn_kernel(const __half* __restrict__ qh, const __half* __restrict__ ql,
            const __half* __restrict__ kh, const __half* __restrict__ vh,
            __half* __restrict__ oh, __half* __restrict__ ol) {
    extern __shared__ char smc[];
    const uint32_t sbase = smem_u32(smc);
    constexpr int QTB = 128 * 72 * 2;   // 18432
    constexpr int TB  = 64 * 72 * 2;    //  9216
    const uint32_t QH = 0, QL = QTB, KH = 2 * QTB, VH = 2 * QTB + TB;
    __half* sp = (__half*)smc;

    const int qt = blockIdx.x, hh = blockIdx.y, bb = blockIdx.z;
    const int tid = threadIdx.x;
    const int warp = tid >> 5, lane = tid & 31;
    const long brow = (long)bb * cfg::T;
    const int hc = hh * cfg::HD;

#pragma unroll
    for (int i = 0; i < 16; i++) {
        int idx = tid + i * 256;
        int rr = idx >> 5, d2 = idx & 31;
        int iq = qt * 128 + rr;
        uint32_t a = 0, c = 0;
        if (iq < cfg::T) {
            a = *(const uint32_t*)(qh + (brow + iq) * cfg::C + hc + d2 * 2);
            c = *(const uint32_t*)(ql + (brow + iq) * cfg::C + hc + d2 * 2);
        }
        *(uint32_t*)(smc + QH + rr * 144 + d2 * 4) = a;
        *(uint32_t*)(smc + QL + rr * 144 + d2 * 4) = c;
    }

    float m0 = -1e30f, m1 = -1e30f, l0 = 0.f, l1 = 0.f;
    float O[8][4];
#pragma unroll
    for (int i = 0; i < 8; i++)
#pragma unroll
        for (int j = 0; j < 4; j++) O[i][j] = 0.f;

    const int wm = warp * 16;
    const int rowg0 = qt * 128 + wm + (lane >> 2);
    const int rowg1 = rowg0 + 8;
    const int chmax = 2 * qt + 1;

    for (int ch = 0; ch <= chmax; ch++) {
        const int kv0 = ch * 64;
        __syncthreads();
#pragma unroll
        for (int i = 0; i < 8; i++) {
            int idx = tid + i * 256;
            int rr = idx >> 5, d2 = idx & 31;
            int jg = kv0 + rr;
            uint32_t ka = 0, va = 0;
            if (jg < cfg::T) {
                ka = *(const uint32_t*)(kh + (brow + jg) * cfg::C + hc + d2 * 2);
                va = *(const uint32_t*)(vh + (brow + jg) * cfg::C + hc + d2 * 2);
            }
            *(uint32_t*)(smc + KH + rr * 144 + d2 * 4) = ka;
            __half2 tv = *reinterpret_cast<__half2*>(&va);
            sp[(VH >> 1) + (2 * d2) * 72 + rr]     = __low2half(tv);
            sp[(VH >> 1) + (2 * d2 + 1) * 72 + rr] = __high2half(tv);
        }
        __syncthreads();

        float S[8][4];
#pragma unroll
        for (int i = 0; i < 8; i++)
#pragma unroll
            for (int j = 0; j < 4; j++) S[i][j] = 0.f;
#pragma unroll
        for (int kk = 0; kk < 64; kk += 16) {
            uint32_t qa_h[4], qa_l[4];
            {
                int r = wm + (lane & 15);
                uint32_t off = r * 144 + ((kk >> 3) + (lane >> 4)) * 16;
                ldm_x4(qa_h, sbase + QH + off);
                ldm_x4(qa_l, sbase + QL + off);
            }
#pragma unroll
            for (int nt = 0; nt < 8; nt++) {
                uint32_t kb_h[2];
                int r = nt * 8 + (lane & 7);
                uint32_t off = r * 144 + ((kk >> 3) + ((lane >> 3) & 1)) * 16;
                ldm_x2(kb_h, sbase + KH + off);
                mma_f16(S[nt], qa_h, kb_h);
                mma_f16(S[nt], qa_l, kb_h);
            }
        }
        const int colb = kv0 + (lane & 3) * 2;
#pragma unroll
        for (int nt = 0; nt < 8; nt++) {
            int c0 = colb + nt * 8, c1 = c0 + 1;
            S[nt][0] = (c0 <= rowg0 && c0 < cfg::T) ? S[nt][0] * cfg::SCALE : -1e30f;
            S[nt][1] = (c1 <= rowg0 && c1 < cfg::T) ? S[nt][1] * cfg::SCALE : -1e30f;
            S[nt][2] = (c0 <= rowg1 && c0 < cfg::T) ? S[nt][2] * cfg::SCALE : -1e30f;
            S[nt][3] = (c1 <= rowg1 && c1 < cfg::T) ? S[nt][3] * cfg::SCALE : -1e30f;
        }
        float mx0 = -1e30f, mx1 = -1e30f;
#pragma unroll
        for (int nt = 0; nt < 8; nt++) {
            mx0 = fmaxf(mx0, fmaxf(S[nt][0], S[nt][1]));
            mx1 = fmaxf(mx1, fmaxf(S[nt][2], S[nt][3]));
        }
        mx0 = fmaxf(mx0, __shfl_xor_sync(~0u, mx0, 1));
        mx0 = fmaxf(mx0, __shfl_xor_sync(~0u, mx0, 2));
        mx1 = fmaxf(mx1, __shfl_xor_sync(~0u, mx1, 1));
        mx1 = fmaxf(mx1, __shfl_xor_sync(~0u, mx1, 2));
        float mn0 = fmaxf(m0, mx0), mn1 = fmaxf(m1, mx1);
        float cr0 = __expf(m0 - mn0), cr1 = __expf(m1 - mn1);
        float ps0 = 0.f, ps1 = 0.f;
#pragma unroll
        for (int nt = 0; nt < 8; nt++) {
            S[nt][0] = __expf(S[nt][0] - mn0); ps0 += S[nt][0];
            S[nt][1] = __expf(S[nt][1] - mn0); ps0 += S[nt][1];
            S[nt][2] = __expf(S[nt][2] - mn1); ps1 += S[nt][2];
            S[nt][3] = __expf(S[nt][3] - mn1); ps1 += S[nt][3];
        }
        ps0 += __shfl_xor_sync(~0u, ps0, 1); ps0 += __shfl_xor_sync(~0u, ps0, 2);
        ps1 += __shfl_xor_sync(~0u, ps1, 1); ps1 += __shfl_xor_sync(~0u, ps1, 2);
        l0 = l0 * cr0 + ps0; l1 = l1 * cr1 + ps1;
        m0 = mn0; m1 = mn1;
#pragma unroll
        for (int nt = 0; nt < 8; nt++) {
            O[nt][0] *= cr0; O[nt][1] *= cr0;
            O[nt][2] *= cr1; O[nt][3] *= cr1;
        }
#pragma unroll
        for (int ks = 0; ks < 4; ks++) {
            uint32_t pa_h[4], pa_l[4];
            split2(S[2 * ks][0],     S[2 * ks][1],     pa_h[0], pa_l[0]);
            split2(S[2 * ks][2],     S[2 * ks][3],     pa_h[1], pa_l[1]);
            split2(S[2 * ks + 1][0], S[2 * ks + 1][1], pa_h[2], pa_l[2]);
            split2(S[2 * ks + 1][2], S[2 * ks + 1][3], pa_h[3], pa_l[3]);
#pragma unroll
            for (int nt2 = 0; nt2 < 8; nt2++) {
                uint32_t vb_h[2];
                int r = nt2 * 8 + (lane & 7);
                uint32_t off = r * 144 + (ks * 2 + ((lane >> 3) & 1)) * 16;
                ldm_x2(vb_h, sbase + VH + off);
                mma_f16(O[nt2], pa_h, vb_h);
                mma_f16(O[nt2], pa_l, vb_h);
            }
        }
    }

    float rl0 = 1.f / l0, rl1 = 1.f / l1;
    const int iq0 = rowg0, iq1 = rowg1;
#pragma unroll
    for (int nt2 = 0; nt2 < 8; nt2++) {
        int col = hc + nt2 * 8 + (lane & 3) * 2;
        if (iq0 < cfg::T) {
            uint32_t h, l;
            split2(O[nt2][0] * rl0, O[nt2][1] * rl0, h, l);
            *(uint32_t*)(oh + (brow + iq0) * cfg::C + col) = h;
            *(uint32_t*)(ol + (brow + iq0) * cfg::C + col) = l;
        }
        if (iq1 < cfg::T) {
            uint32_t h, l;
            split2(O[nt2][2] * rl1, O[nt2][3] * rl1, h, l);
            *(uint32_t*)(oh + (brow + iq1) * cfg::C + col) = h;
            *(uint32_t*)(ol + (brow + iq1) * cfg::C + col) = l;
        }
    }
}

// ---------------------------------------------------------------------------
// Orchestration (graph-capturable)
// ---------------------------------------------------------------------------
extern "C" void kernel_launch(void* const* d_in, const int* in_sizes, int n_in,
                              void* d_out, int out_size) {
    using namespace cfg;
    const float* x     = (const float*)d_in[0];
    const float* dw_w  = (const float*)d_in[1];
    const float* dw_b  = (const float*)d_in[2];
    const float* pw_w  = (const float*)d_in[3];
    const float* pw_b  = (const float*)d_in[4];
    const float* cln_g = (const float*)d_in[5];
    const float* cln_b = (const float*)d_in[6];
    const float* wq = (const float*)d_in[7];  const float* bq = (const float*)d_in[8];
    const float* wk = (const float*)d_in[9];  const float* bk = (const float*)d_in[10];
    const float* wv = (const float*)d_in[11]; const float* bv = (const float*)d_in[12];
    const float* wo = (const float*)d_in[13]; const float* bo = (const float*)d_in[14];
    const float* aln_g = (const float*)d_in[15]; const float* aln_b = (const float*)d_in[16];
    const float* w1 = (const float*)d_in[17]; const float* b1 = (const float*)d_in[18];
    const float* w2 = (const float*)d_in[19]; const float* b2 = (const float*)d_in[20];
    const float* fln_g = (const float*)d_in[21]; const float* fln_b = (const float*)d_in[22];
    float* out = (float*)d_out;

    float* t1;
    __half *a5h, *a5l, *a2h, *a2l, *qh, *ql, *kh, *vh, *whi;
    cudaGetSymbolAddress((void**)&t1,  g_t1);
    cudaGetSymbolAddress((void**)&a5h, g_a512h);
    cudaGetSymbolAddress((void**)&a5l, g_a512l);
    cudaGetSymbolAddress((void**)&a2h, g_a2kh);
    cudaGetSymbolAddress((void**)&a2l, g_a2kl);
    cudaGetSymbolAddress((void**)&qh,  g_qh);
    cudaGetSymbolAddress((void**)&ql,  g_ql);
    cudaGetSymbolAddress((void**)&kh,  g_kh);
    cudaGetSymbolAddress((void**)&vh,  g_vh);
    cudaGetSymbolAddress((void**)&whi, g_whi);

    constexpr int SMEM  = 2 * 3 * 16384;           // tgemm: 98,304 B (double buffer)
    constexpr int ASMEM = 2 * 128 * 72 * 2 + 2 * 64 * 72 * 2;  // attn: 55,296 B
    cudaFuncSetAttribute(tgemm_kernel<0,0>, cudaFuncAttributeMaxDynamicSharedMemorySize, SMEM);
    cudaFuncSetAttribute(tgemm_kernel<0,1>, cudaFuncAttributeMaxDynamicSharedMemorySize, SMEM);
    cudaFuncSetAttribute(tgemm_kernel<0,2>, cudaFuncAttributeMaxDynamicSharedMemorySize, SMEM);
    cudaFuncSetAttribute(tgemm_kernel<1,1>, cudaFuncAttributeMaxDynamicSharedMemorySize, SMEM);
    cudaFuncSetAttribute(attn_kernel,       cudaFuncAttributeMaxDynamicSharedMemorySize, ASMEM);

    auto cvtw = [&](const float* src, long off, long len) {
        cvt_w_kernel<<<(int)((len + 255) / 256), 256>>>(src, whi + off, len);
    };
    cvtw(pw_w, OFF_PW, LEN_PW);
    cvtw(wq,   OFF_WQ, LEN_W);
    cvtw(wk,   OFF_WK, LEN_W);
    cvtw(wv,   OFF_WV, LEN_W);
    cvtw(wo,   OFF_WO, LEN_W);
    cvtw(w1,   OFF_W1, LEN_W1);
    cvtw(w2,   OFF_W2, LEN_W2);
    zero_pad_kernel<<<(64 * 2048 + 255) / 256, 256>>>(a5h, a5l, a2h, a2l);

    dim3 gCC(C / 128, MPAD / 128);      // (4, 63)
    dim3 gCH(HID / 128, MPAD / 128);    // (16, 63)
    float* nullf = nullptr;
    __half* nullh = nullptr;

    const float* cur = x;
    for (int l = 0; l < L; l++) {
        // ---- conv block 1 ----
        long i0 = (long)(l * NC + 0);
        dwconv_kernel<<<BT, C>>>(cur, dw_w + i0 * C * K, dw_b + i0 * C, a5h, a5l);
        tgemm_kernel<0,0><<<gCC, 256, SMEM>>>(a5h, a5l, whi + OFF_PW + i0 * C * C,
            pw_b + i0 * C, t1, nullh, nullh, BT, C, C);
        ln_kernel<0><<<BT, 256>>>(t1, cln_g + i0 * C, cln_b + i0 * C, nullh, nullh);
        // ---- conv block 2 ----
        long i1 = (long)(l * NC + 1);
        dwconv_kernel<<<BT, C>>>(t1, dw_w + i1 * C * K, dw_b + i1 * C, a5h, a5l);
        tgemm_kernel<0,0><<<gCC, 256, SMEM>>>(a5h, a5l, whi + OFF_PW + i1 * C * C,
            pw_b + i1 * C, t1, nullh, nullh, BT, C, C);
        ln_kernel<2><<<BT, 256>>>(t1, cln_g + i1 * C, cln_b + i1 * C, a5h, a5l);
        // ---- attention ----
        long lw = (long)l * C * C;
        tgemm_kernel<0,1><<<gCC, 256, SMEM>>>(a5h, a5l, whi + OFF_WQ + lw,
            bq + (long)l * C, nullf, qh, ql, BT, C, C);
        tgemm_kernel<0,2><<<gCC, 256, SMEM>>>(a5h, a5l, whi + OFF_WK + lw,
            bk + (long)l * C, nullf, kh, nullh, BT, C, C);
        tgemm_kernel<0,2><<<gCC, 256, SMEM>>>(a5h, a5l, whi + OFF_WV + lw,
            bv + (long)l * C, nullf, vh, nullh, BT, C, C);
        attn_kernel<<<dim3(4, NH, B), 256, ASMEM>>>(qh, ql, kh, vh, a5h, a5l);
        tgemm_kernel<0,0><<<gCC, 256, SMEM>>>(a5h, a5l, whi + OFF_WO + lw,
            bo + (long)l * C, t1, nullh, nullh, BT, C, C);
        ln_kernel<2><<<BT, 256>>>(t1, aln_g + (long)l * C, aln_b + (long)l * C, a5h, a5l);
        // ---- FFN ----
        tgemm_kernel<1,1><<<gCH, 256, SMEM>>>(a5h, a5l, whi + OFF_W1 + (long)l * HID * C,
            b1 + (long)l * HID, nullf, a2h, a2l, BT, HID, C);
        float* outl = out + (long)l * BTC;
        tgemm_kernel<0,0><<<gCC, 256, SMEM>>>(a2h, a2l, whi + OFF_W2 + (long)l * C * HID,
            b2 + (long)l * C, outl, nullh, nullh, BT, C, HID);
        ln_kernel<0><<<BT, 256>>>(outl, fln_g + (long)l * C, fln_b + (long)l * C, nullh, nullh);
        cur = outl;
    }
}